// round 1
// baseline (speedup 1.0000x reference)
#include <cuda_runtime.h>
#include <math.h>

#define HSZ   1024
#define NHEADS 16
#define HDIM  64
#define BATCH 2
#define SEQ   2048
#define NTOK  (BATCH*SEQ)   /* 4096 */

// -------- scratch (allocation-free rule: __device__ globals) --------
__device__ float g_xn[(size_t)NTOK * HSZ];                 // 16 MB
__device__ float g_gate[NTOK];                             // 16 KB
__device__ float g_qkv[(size_t)NTOK * 3 * HSZ];            // 48 MB
__device__ float g_att[(size_t)NTOK * HSZ];                // 16 MB

// ============================================================
// Kernel 1: LayerNorm + entropy gate (one block per token)
// ============================================================
__global__ __launch_bounds__(256) void ln_gate_kernel(
    const float* __restrict__ x,
    const float* __restrict__ lng,
    const float* __restrict__ lnb,
    const float* __restrict__ w_ent,
    const float* __restrict__ b_ent)
{
    __shared__ float sbuf[8];
    const int t   = blockIdx.x;
    const int tid = threadIdx.x;
    const float* xr = x + (size_t)t * HSZ;

    float v[4];
    float s = 0.f;
#pragma unroll
    for (int r = 0; r < 4; r++) { v[r] = xr[tid + r * 256]; s += v[r]; }

    // block reduce (sum)
#pragma unroll
    for (int off = 16; off; off >>= 1) s += __shfl_xor_sync(0xffffffffu, s, off);
    if ((tid & 31) == 0) sbuf[tid >> 5] = s;
    __syncthreads();
    float tot = 0.f;
#pragma unroll
    for (int i = 0; i < 8; i++) tot += sbuf[i];
    __syncthreads();
    const float mu = tot * (1.f / HSZ);

    float s2 = 0.f;
#pragma unroll
    for (int r = 0; r < 4; r++) { float d = v[r] - mu; s2 += d * d; }
#pragma unroll
    for (int off = 16; off; off >>= 1) s2 += __shfl_xor_sync(0xffffffffu, s2, off);
    if ((tid & 31) == 0) sbuf[tid >> 5] = s2;
    __syncthreads();
    float tot2 = 0.f;
#pragma unroll
    for (int i = 0; i < 8; i++) tot2 += sbuf[i];
    __syncthreads();
    const float rstd = rsqrtf(tot2 * (1.f / HSZ) + 1e-6f);

    float e = 0.f;
#pragma unroll
    for (int r = 0; r < 4; r++) {
        const int idx = tid + r * 256;
        const float xn = (v[r] - mu) * rstd * lng[idx] + lnb[idx];
        g_xn[(size_t)t * HSZ + idx] = xn;
        e += xn * w_ent[idx];
    }
#pragma unroll
    for (int off = 16; off; off >>= 1) e += __shfl_xor_sync(0xffffffffu, e, off);
    if ((tid & 31) == 0) sbuf[tid >> 5] = e;
    __syncthreads();
    if (tid == 0) {
        float et = 0.f;
#pragma unroll
        for (int i = 0; i < 8; i++) et += sbuf[i];
        float gt = 1.f / (1.f + __expf(-(et + b_ent[0])));
        g_gate[t] = fminf(fmaxf(gt, 0.1f), 2.0f);
    }
}

// ============================================================
// Kernel 2: SGEMM  C[m,n] = alpha * (sum_k A[m,k]*Bw[n,k] + bias[n])
// A: [M,K] row-major, Bw: [N,K] row-major (i.e. C = A @ Bw^T)
// BM=BN=128, BK=16, 256 threads, 8x8 per thread.
// Requires M%128==0, N%128==0, K%16==0.
// ============================================================
__global__ __launch_bounds__(256) void sgemm_tn(
    const float* __restrict__ A, const float* __restrict__ Bw,
    const float* __restrict__ bias, float* __restrict__ C,
    int M, int N, int K, float alpha)
{
    __shared__ float As[16][128];
    __shared__ float Bs[16][128];
    const int tid = threadIdx.x;
    const int tx = tid & 15, ty = tid >> 4;
    const int m0 = blockIdx.y * 128, n0 = blockIdx.x * 128;
    const int lrow = tid >> 2;          // 0..63
    const int lk   = (tid & 3) << 2;    // 0,4,8,12

    float acc[8][8];
#pragma unroll
    for (int i = 0; i < 8; i++)
#pragma unroll
        for (int j = 0; j < 8; j++) acc[i][j] = 0.f;

    for (int k0 = 0; k0 < K; k0 += 16) {
#pragma unroll
        for (int r = 0; r < 2; r++) {
            const int row = lrow + (r << 6);
            float4 a = *(const float4*)(A + (size_t)(m0 + row) * K + k0 + lk);
            As[lk + 0][row] = a.x; As[lk + 1][row] = a.y;
            As[lk + 2][row] = a.z; As[lk + 3][row] = a.w;
            float4 b = *(const float4*)(Bw + (size_t)(n0 + row) * K + k0 + lk);
            Bs[lk + 0][row] = b.x; Bs[lk + 1][row] = b.y;
            Bs[lk + 2][row] = b.z; Bs[lk + 3][row] = b.w;
        }
        __syncthreads();
#pragma unroll
        for (int kk = 0; kk < 16; kk++) {
            float ar[8], br[8];
#pragma unroll
            for (int i = 0; i < 8; i++) ar[i] = As[kk][(ty << 3) + i];
#pragma unroll
            for (int j = 0; j < 8; j++) br[j] = Bs[kk][(tx << 3) + j];
#pragma unroll
            for (int i = 0; i < 8; i++)
#pragma unroll
                for (int j = 0; j < 8; j++)
                    acc[i][j] = fmaf(ar[i], br[j], acc[i][j]);
        }
        __syncthreads();
    }

    float bj[8];
#pragma unroll
    for (int j = 0; j < 8; j++) bj[j] = bias[n0 + (tx << 3) + j];
#pragma unroll
    for (int i = 0; i < 8; i++) {
        float4 o0, o1;
        o0.x = alpha * (acc[i][0] + bj[0]); o0.y = alpha * (acc[i][1] + bj[1]);
        o0.z = alpha * (acc[i][2] + bj[2]); o0.w = alpha * (acc[i][3] + bj[3]);
        o1.x = alpha * (acc[i][4] + bj[4]); o1.y = alpha * (acc[i][5] + bj[5]);
        o1.z = alpha * (acc[i][6] + bj[6]); o1.w = alpha * (acc[i][7] + bj[7]);
        float* cp = C + (size_t)(m0 + (ty << 3) + i) * N + n0 + (tx << 3);
        *(float4*)(cp)     = o0;
        *(float4*)(cp + 4) = o1;
    }
}

// ============================================================
// Kernel 3: causal flash attention with temp=0.1 and per-key gate
// grid (S/64, NH, B), 256 threads. out = (sum p*gate*v) / (sum p)
// qkv layout: [token][3*H], q at +h*64, k at +1024+h*64, v at +2048+h*64
// ============================================================
#define BQ  64
#define PADL 65

__global__ __launch_bounds__(256) void attn_kernel(float* __restrict__ att)
{
    extern __shared__ float sm[];
    float* Qs = sm;                  // [64][65]
    float* Ks = Qs + 64 * PADL;      // [64][65]
    float* Vs = Ks + 64 * PADL;      // [64][65]
    float* Ps = Vs + 64 * PADL;      // [64][65]
    float* gs = Ps + 64 * PADL;      // [64]

    const int qt = blockIdx.x, h = blockIdx.y, b = blockIdx.z;
    const int tid = threadIdx.x;
    const int tx = tid & 15, ty = tid >> 4;
    const int q0 = qt * BQ;
    const float sc = 1.25f;          // (1/sqrt(64)) / 0.1

    // load Q tile
#pragma unroll
    for (int r = 0; r < 4; r++) {
        const int row = (tid >> 4) + r * 16;
        const int d   = (tid & 15) << 2;
        float4 qv = *(const float4*)&g_qkv[(size_t)(b * SEQ + q0 + row) * 3072 + h * 64 + d];
        Qs[row * PADL + d + 0] = qv.x; Qs[row * PADL + d + 1] = qv.y;
        Qs[row * PADL + d + 2] = qv.z; Qs[row * PADL + d + 3] = qv.w;
    }

    float m_i[4], l_i[4], acc[4][4];
#pragma unroll
    for (int i = 0; i < 4; i++) {
        m_i[i] = -INFINITY; l_i[i] = 0.f;
#pragma unroll
        for (int j = 0; j < 4; j++) acc[i][j] = 0.f;
    }

    const int nkt = qt + 1;
    for (int kt = 0; kt < nkt; kt++) {
        const int k0 = kt * BQ;
        __syncthreads();  // previous tile fully consumed; Q visible on first iter
#pragma unroll
        for (int r = 0; r < 4; r++) {
            const int row = (tid >> 4) + r * 16;
            const int d   = (tid & 15) << 2;
            const size_t base = (size_t)(b * SEQ + k0 + row) * 3072 + h * 64 + d;
            float4 kv = *(const float4*)&g_qkv[base + 1024];
            Ks[row * PADL + d + 0] = kv.x; Ks[row * PADL + d + 1] = kv.y;
            Ks[row * PADL + d + 2] = kv.z; Ks[row * PADL + d + 3] = kv.w;
            float4 vv = *(const float4*)&g_qkv[base + 2048];
            Vs[row * PADL + d + 0] = vv.x; Vs[row * PADL + d + 1] = vv.y;
            Vs[row * PADL + d + 2] = vv.z; Vs[row * PADL + d + 3] = vv.w;
        }
        if (tid < 64) gs[tid] = g_gate[b * SEQ + k0 + tid];
        __syncthreads();

        // scores s[4][4]
        float s[4][4];
#pragma unroll
        for (int i = 0; i < 4; i++)
#pragma unroll
            for (int j = 0; j < 4; j++) s[i][j] = 0.f;
#pragma unroll 8
        for (int d = 0; d < 64; d++) {
            float qr[4], kr[4];
#pragma unroll
            for (int i = 0; i < 4; i++) qr[i] = Qs[((ty << 2) + i) * PADL + d];
#pragma unroll
            for (int j = 0; j < 4; j++) kr[j] = Ks[((tx << 2) + j) * PADL + d];
#pragma unroll
            for (int i = 0; i < 4; i++)
#pragma unroll
                for (int j = 0; j < 4; j++)
                    s[i][j] = fmaf(qr[i], kr[j], s[i][j]);
        }

        const bool diag = (kt == qt);
#pragma unroll
        for (int i = 0; i < 4; i++) {
            const int gq = q0 + (ty << 2) + i;
#pragma unroll
            for (int j = 0; j < 4; j++) {
                s[i][j] *= sc;
                if (diag && (k0 + (tx << 2) + j) > gq) s[i][j] = -INFINITY;
            }
        }

        // online softmax update (per q-row, reduced over the 16 tx lanes)
#pragma unroll
        for (int i = 0; i < 4; i++) {
            float tm = fmaxf(fmaxf(s[i][0], s[i][1]), fmaxf(s[i][2], s[i][3]));
#pragma unroll
            for (int off = 1; off < 16; off <<= 1)
                tm = fmaxf(tm, __shfl_xor_sync(0xffffffffu, tm, off));
            const float nm = fmaxf(m_i[i], tm);
            const float al = __expf(m_i[i] - nm);
            float rs = 0.f;
#pragma unroll
            for (int j = 0; j < 4; j++) {
                const float p = __expf(s[i][j] - nm);
                s[i][j] = p;
                rs += p;
            }
#pragma unroll
            for (int off = 1; off < 16; off <<= 1)
                rs += __shfl_xor_sync(0xffffffffu, rs, off);
            l_i[i] = l_i[i] * al + rs;
            m_i[i] = nm;
#pragma unroll
            for (int j = 0; j < 4; j++) acc[i][j] *= al;
        }

        // P (with gate) to shared
#pragma unroll
        for (int i = 0; i < 4; i++)
#pragma unroll
            for (int j = 0; j < 4; j++)
                Ps[((ty << 2) + i) * PADL + (tx << 2) + j] = s[i][j] * gs[(tx << 2) + j];
        __syncthreads();

        // PV accumulate: acc[i][jd] += sum_kc Ps[qr][kc]*Vs[kc][d]
#pragma unroll 8
        for (int kc = 0; kc < 64; kc++) {
            float pr[4], vr[4];
#pragma unroll
            for (int i = 0; i < 4; i++) pr[i] = Ps[((ty << 2) + i) * PADL + kc];
#pragma unroll
            for (int j = 0; j < 4; j++) vr[j] = Vs[kc * PADL + (tx << 2) + j];
#pragma unroll
            for (int i = 0; i < 4; i++)
#pragma unroll
                for (int j = 0; j < 4; j++)
                    acc[i][j] = fmaf(pr[i], vr[j], acc[i][j]);
        }
    }

    // write merged-head layout: att[token][h*64 + d]
#pragma unroll
    for (int i = 0; i < 4; i++) {
        const float inv = 1.f / l_i[i];
        float4 o;
        o.x = acc[i][0] * inv; o.y = acc[i][1] * inv;
        o.z = acc[i][2] * inv; o.w = acc[i][3] * inv;
        *(float4*)&att[(size_t)(b * SEQ + q0 + (ty << 2) + i) * HSZ + h * 64 + (tx << 2)] = o;
    }
}

// ============================================================
// host launcher
// ============================================================
extern "C" void kernel_launch(void* const* d_in, const int* in_sizes, int n_in,
                              void* d_out, int out_size)
{
    const float* x     = (const float*)d_in[0];
    const float* ln_g  = (const float*)d_in[1];
    const float* ln_b  = (const float*)d_in[2];
    const float* w_qkv = (const float*)d_in[3];
    const float* b_qkv = (const float*)d_in[4];
    const float* w_ent = (const float*)d_in[5];
    const float* b_ent = (const float*)d_in[6];
    const float* w_out = (const float*)d_in[7];
    const float* b_out = (const float*)d_in[8];
    float* out = (float*)d_out;

    void *p_xn, *p_qkv, *p_att;
    cudaGetSymbolAddress(&p_xn,  g_xn);
    cudaGetSymbolAddress(&p_qkv, g_qkv);
    cudaGetSymbolAddress(&p_att, g_att);

    // 1) LN + entropy gate
    ln_gate_kernel<<<NTOK, 256>>>(x, ln_g, ln_b, w_ent, b_ent);

    // 2) QKV projection: [4096,1024] @ [3072,1024]^T -> [4096,3072]
    sgemm_tn<<<dim3(3 * HSZ / 128, NTOK / 128), 256>>>(
        (const float*)p_xn, w_qkv, b_qkv, (float*)p_qkv,
        NTOK, 3 * HSZ, HSZ, 1.0f);

    // 3) attention
    const int smem = (4 * 64 * PADL + 64) * (int)sizeof(float);  // 66816 B
    cudaFuncSetAttribute(attn_kernel, cudaFuncAttributeMaxDynamicSharedMemorySize, smem);
    attn_kernel<<<dim3(SEQ / BQ, NHEADS, BATCH), 256, smem>>>((float*)p_att);

    // 4) output projection: ([4096,1024] @ [1024,1024]^T + b) * 0.1
    sgemm_tn<<<dim3(HSZ / 128, NTOK / 128), 256>>>(
        (const float*)p_att, w_out, b_out, out,
        NTOK, HSZ, HSZ, 0.1f);
}

// round 2
// speedup vs baseline: 1.1493x; 1.1493x over previous
#include <cuda_runtime.h>
#include <math.h>

#define HSZ   1024
#define NHEADS 16
#define HDIM  64
#define BATCH 2
#define SEQ   2048
#define NTOK  (BATCH*SEQ)   /* 4096 */

// -------- scratch (allocation-free rule: __device__ globals) --------
__device__ float g_xn[(size_t)NTOK * HSZ];                 // 16 MB
__device__ float g_gate[NTOK];                             // 16 KB
__device__ float g_qkv[(size_t)NTOK * 3 * HSZ];            // 48 MB
__device__ float g_att[(size_t)NTOK * HSZ];                // 16 MB

// ============================================================
// Kernel 1: LayerNorm + entropy gate (one block per token)
// ============================================================
__global__ __launch_bounds__(256) void ln_gate_kernel(
    const float* __restrict__ x,
    const float* __restrict__ lng,
    const float* __restrict__ lnb,
    const float* __restrict__ w_ent,
    const float* __restrict__ b_ent)
{
    __shared__ float sbuf[8];
    const int t   = blockIdx.x;
    const int tid = threadIdx.x;
    const float* xr = x + (size_t)t * HSZ;

    float v[4];
    float s = 0.f;
#pragma unroll
    for (int r = 0; r < 4; r++) { v[r] = xr[tid + r * 256]; s += v[r]; }

#pragma unroll
    for (int off = 16; off; off >>= 1) s += __shfl_xor_sync(0xffffffffu, s, off);
    if ((tid & 31) == 0) sbuf[tid >> 5] = s;
    __syncthreads();
    float tot = 0.f;
#pragma unroll
    for (int i = 0; i < 8; i++) tot += sbuf[i];
    __syncthreads();
    const float mu = tot * (1.f / HSZ);

    float s2 = 0.f;
#pragma unroll
    for (int r = 0; r < 4; r++) { float d = v[r] - mu; s2 += d * d; }
#pragma unroll
    for (int off = 16; off; off >>= 1) s2 += __shfl_xor_sync(0xffffffffu, s2, off);
    if ((tid & 31) == 0) sbuf[tid >> 5] = s2;
    __syncthreads();
    float tot2 = 0.f;
#pragma unroll
    for (int i = 0; i < 8; i++) tot2 += sbuf[i];
    __syncthreads();
    const float rstd = rsqrtf(tot2 * (1.f / HSZ) + 1e-6f);

    float e = 0.f;
#pragma unroll
    for (int r = 0; r < 4; r++) {
        const int idx = tid + r * 256;
        const float xn = (v[r] - mu) * rstd * lng[idx] + lnb[idx];
        g_xn[(size_t)t * HSZ + idx] = xn;
        e += xn * w_ent[idx];
    }
#pragma unroll
    for (int off = 16; off; off >>= 1) e += __shfl_xor_sync(0xffffffffu, e, off);
    if ((tid & 31) == 0) sbuf[tid >> 5] = e;
    __syncthreads();
    if (tid == 0) {
        float et = 0.f;
#pragma unroll
        for (int i = 0; i < 8; i++) et += sbuf[i];
        float gt = 1.f / (1.f + __expf(-(et + b_ent[0])));
        g_gate[t] = fminf(fmaxf(gt, 0.1f), 2.0f);
    }
}

// ============================================================
// Kernel 2: double-buffered SGEMM  C = alpha*(A @ Bw^T + bias)
// A:[M,K] rm, Bw:[N,K] rm. BM=BN=128, BK=16, 256 thr, 8x8/thread.
// ============================================================
__global__ __launch_bounds__(256, 2) void sgemm_tn(
    const float* __restrict__ A, const float* __restrict__ Bw,
    const float* __restrict__ bias, float* __restrict__ C,
    int M, int N, int K, float alpha)
{
    __shared__ float As[2][16][132];
    __shared__ float Bs[2][16][132];
    const int tid = threadIdx.x;
    const int tx = tid & 15, ty = tid >> 4;
    const int m0 = blockIdx.y * 128, n0 = blockIdx.x * 128;
    const int lrow = tid >> 2;           // 0..63
    const int lk   = (tid & 3) << 2;     // 0,4,8,12

    float4 pa0, pa1, pb0, pb1;

    // prologue: tile 0 -> buffer 0
    pa0 = *(const float4*)(A  + (size_t)(m0 + lrow)      * K + lk);
    pa1 = *(const float4*)(A  + (size_t)(m0 + lrow + 64) * K + lk);
    pb0 = *(const float4*)(Bw + (size_t)(n0 + lrow)      * K + lk);
    pb1 = *(const float4*)(Bw + (size_t)(n0 + lrow + 64) * K + lk);
    As[0][lk+0][lrow] = pa0.x; As[0][lk+1][lrow] = pa0.y;
    As[0][lk+2][lrow] = pa0.z; As[0][lk+3][lrow] = pa0.w;
    As[0][lk+0][lrow+64] = pa1.x; As[0][lk+1][lrow+64] = pa1.y;
    As[0][lk+2][lrow+64] = pa1.z; As[0][lk+3][lrow+64] = pa1.w;
    Bs[0][lk+0][lrow] = pb0.x; Bs[0][lk+1][lrow] = pb0.y;
    Bs[0][lk+2][lrow] = pb0.z; Bs[0][lk+3][lrow] = pb0.w;
    Bs[0][lk+0][lrow+64] = pb1.x; Bs[0][lk+1][lrow+64] = pb1.y;
    Bs[0][lk+2][lrow+64] = pb1.z; Bs[0][lk+3][lrow+64] = pb1.w;
    __syncthreads();

    float acc[8][8];
#pragma unroll
    for (int i = 0; i < 8; i++)
#pragma unroll
        for (int j = 0; j < 8; j++) acc[i][j] = 0.f;

    int cur = 0;
    for (int k0 = 16; k0 <= K; k0 += 16) {
        if (k0 < K) {
            pa0 = *(const float4*)(A  + (size_t)(m0 + lrow)      * K + k0 + lk);
            pa1 = *(const float4*)(A  + (size_t)(m0 + lrow + 64) * K + k0 + lk);
            pb0 = *(const float4*)(Bw + (size_t)(n0 + lrow)      * K + k0 + lk);
            pb1 = *(const float4*)(Bw + (size_t)(n0 + lrow + 64) * K + k0 + lk);
        }
#pragma unroll
        for (int kk = 0; kk < 16; kk++) {
            float4 a0 = *(const float4*)&As[cur][kk][ty << 3];
            float4 a1 = *(const float4*)&As[cur][kk][(ty << 3) + 4];
            float4 b0 = *(const float4*)&Bs[cur][kk][tx << 3];
            float4 b1 = *(const float4*)&Bs[cur][kk][(tx << 3) + 4];
            float ar[8] = {a0.x, a0.y, a0.z, a0.w, a1.x, a1.y, a1.z, a1.w};
            float br[8] = {b0.x, b0.y, b0.z, b0.w, b1.x, b1.y, b1.z, b1.w};
#pragma unroll
            for (int i = 0; i < 8; i++)
#pragma unroll
                for (int j = 0; j < 8; j++)
                    acc[i][j] = fmaf(ar[i], br[j], acc[i][j]);
        }
        if (k0 < K) {
            const int nxt = cur ^ 1;
            As[nxt][lk+0][lrow] = pa0.x; As[nxt][lk+1][lrow] = pa0.y;
            As[nxt][lk+2][lrow] = pa0.z; As[nxt][lk+3][lrow] = pa0.w;
            As[nxt][lk+0][lrow+64] = pa1.x; As[nxt][lk+1][lrow+64] = pa1.y;
            As[nxt][lk+2][lrow+64] = pa1.z; As[nxt][lk+3][lrow+64] = pa1.w;
            Bs[nxt][lk+0][lrow] = pb0.x; Bs[nxt][lk+1][lrow] = pb0.y;
            Bs[nxt][lk+2][lrow] = pb0.z; Bs[nxt][lk+3][lrow] = pb0.w;
            Bs[nxt][lk+0][lrow+64] = pb1.x; Bs[nxt][lk+1][lrow+64] = pb1.y;
            Bs[nxt][lk+2][lrow+64] = pb1.z; Bs[nxt][lk+3][lrow+64] = pb1.w;
            __syncthreads();
            cur = nxt;
        }
    }

    float bj[8];
#pragma unroll
    for (int j = 0; j < 8; j++) bj[j] = bias[n0 + (tx << 3) + j];
#pragma unroll
    for (int i = 0; i < 8; i++) {
        float4 o0, o1;
        o0.x = alpha * (acc[i][0] + bj[0]); o0.y = alpha * (acc[i][1] + bj[1]);
        o0.z = alpha * (acc[i][2] + bj[2]); o0.w = alpha * (acc[i][3] + bj[3]);
        o1.x = alpha * (acc[i][4] + bj[4]); o1.y = alpha * (acc[i][5] + bj[5]);
        o1.z = alpha * (acc[i][6] + bj[6]); o1.w = alpha * (acc[i][7] + bj[7]);
        float* cp = C + (size_t)(m0 + (ty << 3) + i) * N + n0 + (tx << 3);
        *(float4*)(cp)     = o0;
        *(float4*)(cp + 4) = o1;
    }
}

// ============================================================
// Kernel 3: causal flash attention, temp=0.1, per-key gate
// 128q x 64k tiles, 256 threads, 8x4 per thread.
// gate folded into V at load; out = (sum p*g*v) / (sum p)
// ============================================================
#define AQ 128
#define AK 64
#define APAD 68

__global__ __launch_bounds__(256, 1) void attn_kernel(float* __restrict__ att)
{
    extern __shared__ float sm[];
    float* Qs = sm;                      // [128][68]
    float* Ks = Qs + AQ * APAD;          // [64][68]
    float* Vs = Ks + AK * APAD;          // [64][68]  (pre-gated)
    float* Ps = Vs + AK * APAD;          // [128][68]

    const int qt = gridDim.x - 1 - blockIdx.x;   // big tiles first
    const int h = blockIdx.y, b = blockIdx.z;
    const int tid = threadIdx.x;
    const int tx = tid & 15, ty = tid >> 4;
    const int q0 = qt * AQ;
    const float sc = 1.25f;              // (1/sqrt(64)) / 0.1  (exp-units)

    // load Q tile: 128 rows x 64 d
#pragma unroll
    for (int r = 0; r < 8; r++) {
        const int idx = tid + r * 256;
        const int row = idx >> 4;
        const int d4  = (idx & 15) << 2;
        float4 qv = *(const float4*)&g_qkv[(size_t)(b * SEQ + q0 + row) * 3072 + h * 64 + d4];
        Qs[row * APAD + d4 + 0] = qv.x; Qs[row * APAD + d4 + 1] = qv.y;
        Qs[row * APAD + d4 + 2] = qv.z; Qs[row * APAD + d4 + 3] = qv.w;
    }

    float m_i[8], l_i[8], acc[8][4];
#pragma unroll
    for (int i = 0; i < 8; i++) {
        m_i[i] = -INFINITY; l_i[i] = 0.f;
#pragma unroll
        for (int j = 0; j < 4; j++) acc[i][j] = 0.f;
    }

    const int nkt = 2 * qt + 2;
    for (int kt = 0; kt < nkt; kt++) {
        const int k0 = kt * AK;
        __syncthreads();   // prev tile consumed (and Q visible on first iter)
#pragma unroll
        for (int r = 0; r < 4; r++) {
            const int idx = tid + r * 256;
            const int row = idx >> 4;
            const int d4  = (idx & 15) << 2;
            const size_t base = (size_t)(b * SEQ + k0 + row) * 3072 + h * 64 + d4;
            float4 kv = *(const float4*)&g_qkv[base + 1024];
            Ks[row * APAD + d4 + 0] = kv.x; Ks[row * APAD + d4 + 1] = kv.y;
            Ks[row * APAD + d4 + 2] = kv.z; Ks[row * APAD + d4 + 3] = kv.w;
            const float g = g_gate[b * SEQ + k0 + row];
            float4 vv = *(const float4*)&g_qkv[base + 2048];
            Vs[row * APAD + d4 + 0] = vv.x * g; Vs[row * APAD + d4 + 1] = vv.y * g;
            Vs[row * APAD + d4 + 2] = vv.z * g; Vs[row * APAD + d4 + 3] = vv.w * g;
        }
        __syncthreads();

        // scores s[8][4]
        float s[8][4];
#pragma unroll
        for (int i = 0; i < 8; i++)
#pragma unroll
            for (int j = 0; j < 4; j++) s[i][j] = 0.f;

#pragma unroll 4
        for (int d = 0; d < 64; d += 4) {
            float4 kr[4];
#pragma unroll
            for (int j = 0; j < 4; j++)
                kr[j] = *(const float4*)&Ks[((tx << 2) + j) * APAD + d];
#pragma unroll
            for (int i = 0; i < 8; i++) {
                float4 q = *(const float4*)&Qs[((ty << 3) + i) * APAD + d];
#pragma unroll
                for (int j = 0; j < 4; j++) {
                    s[i][j] = fmaf(q.x, kr[j].x, s[i][j]);
                    s[i][j] = fmaf(q.y, kr[j].y, s[i][j]);
                    s[i][j] = fmaf(q.z, kr[j].z, s[i][j]);
                    s[i][j] = fmaf(q.w, kr[j].w, s[i][j]);
                }
            }
        }

        // scale + causal mask (only the two diagonal tiles need it)
        if (kt >= 2 * qt) {
#pragma unroll
            for (int i = 0; i < 8; i++) {
                const int gq = q0 + (ty << 3) + i;
#pragma unroll
                for (int j = 0; j < 4; j++) {
                    s[i][j] *= sc;
                    if ((k0 + (tx << 2) + j) > gq) s[i][j] = -INFINITY;
                }
            }
        } else {
#pragma unroll
            for (int i = 0; i < 8; i++)
#pragma unroll
                for (int j = 0; j < 4; j++) s[i][j] *= sc;
        }

        // online softmax (reduce over the 16 tx lanes)
#pragma unroll
        for (int i = 0; i < 8; i++) {
            float tm = fmaxf(fmaxf(s[i][0], s[i][1]), fmaxf(s[i][2], s[i][3]));
#pragma unroll
            for (int off = 1; off < 16; off <<= 1)
                tm = fmaxf(tm, __shfl_xor_sync(0xffffffffu, tm, off));
            const float nm = fmaxf(m_i[i], tm);
            const float al = __expf(m_i[i] - nm);
            float rs = 0.f;
#pragma unroll
            for (int j = 0; j < 4; j++) {
                const float p = __expf(s[i][j] - nm);
                s[i][j] = p;
                rs += p;
            }
#pragma unroll
            for (int off = 1; off < 16; off <<= 1)
                rs += __shfl_xor_sync(0xffffffffu, rs, off);
            l_i[i] = l_i[i] * al + rs;
            m_i[i] = nm;
#pragma unroll
            for (int j = 0; j < 4; j++) acc[i][j] *= al;
        }

        // P to shared (plain p; gate already in V)
#pragma unroll
        for (int i = 0; i < 8; i++) {
            float4 pv4;
            pv4.x = s[i][0]; pv4.y = s[i][1]; pv4.z = s[i][2]; pv4.w = s[i][3];
            *(float4*)&Ps[((ty << 3) + i) * APAD + (tx << 2)] = pv4;
        }
        __syncthreads();

        // PV: acc[i][d] += sum_kc P[i][kc] * V[kc][d]
#pragma unroll 4
        for (int kc = 0; kc < 64; kc += 4) {
            float4 vr[4];
#pragma unroll
            for (int jj = 0; jj < 4; jj++)
                vr[jj] = *(const float4*)&Vs[(kc + jj) * APAD + (tx << 2)];
#pragma unroll
            for (int i = 0; i < 8; i++) {
                float4 p = *(const float4*)&Ps[((ty << 3) + i) * APAD + kc];
                acc[i][0] = fmaf(p.x, vr[0].x, acc[i][0]);
                acc[i][0] = fmaf(p.y, vr[1].x, acc[i][0]);
                acc[i][0] = fmaf(p.z, vr[2].x, acc[i][0]);
                acc[i][0] = fmaf(p.w, vr[3].x, acc[i][0]);
                acc[i][1] = fmaf(p.x, vr[0].y, acc[i][1]);
                acc[i][1] = fmaf(p.y, vr[1].y, acc[i][1]);
                acc[i][1] = fmaf(p.z, vr[2].y, acc[i][1]);
                acc[i][1] = fmaf(p.w, vr[3].y, acc[i][1]);
                acc[i][2] = fmaf(p.x, vr[0].z, acc[i][2]);
                acc[i][2] = fmaf(p.y, vr[1].z, acc[i][2]);
                acc[i][2] = fmaf(p.z, vr[2].z, acc[i][2]);
                acc[i][2] = fmaf(p.w, vr[3].z, acc[i][2]);
                acc[i][3] = fmaf(p.x, vr[0].w, acc[i][3]);
                acc[i][3] = fmaf(p.y, vr[1].w, acc[i][3]);
                acc[i][3] = fmaf(p.z, vr[2].w, acc[i][3]);
                acc[i][3] = fmaf(p.w, vr[3].w, acc[i][3]);
            }
        }
    }

    // epilogue: normalize, write merged-head layout att[token][h*64+d]
#pragma unroll
    for (int i = 0; i < 8; i++) {
        const float inv = 1.f / l_i[i];
        float4 o;
        o.x = acc[i][0] * inv; o.y = acc[i][1] * inv;
        o.z = acc[i][2] * inv; o.w = acc[i][3] * inv;
        *(float4*)&att[(size_t)(b * SEQ + q0 + (ty << 3) + i) * HSZ + h * 64 + (tx << 2)] = o;
    }
}

// ============================================================
// host launcher
// ============================================================
extern "C" void kernel_launch(void* const* d_in, const int* in_sizes, int n_in,
                              void* d_out, int out_size)
{
    const float* x     = (const float*)d_in[0];
    const float* ln_g  = (const float*)d_in[1];
    const float* ln_b  = (const float*)d_in[2];
    const float* w_qkv = (const float*)d_in[3];
    const float* b_qkv = (const float*)d_in[4];
    const float* w_ent = (const float*)d_in[5];
    const float* b_ent = (const float*)d_in[6];
    const float* w_out = (const float*)d_in[7];
    const float* b_out = (const float*)d_in[8];
    float* out = (float*)d_out;

    void *p_xn, *p_qkv, *p_att;
    cudaGetSymbolAddress(&p_xn,  g_xn);
    cudaGetSymbolAddress(&p_qkv, g_qkv);
    cudaGetSymbolAddress(&p_att, g_att);

    // 1) LN + entropy gate
    ln_gate_kernel<<<NTOK, 256>>>(x, ln_g, ln_b, w_ent, b_ent);

    // 2) QKV projection: [4096,1024] @ [3072,1024]^T -> [4096,3072]
    sgemm_tn<<<dim3(3 * HSZ / 128, NTOK / 128), 256>>>(
        (const float*)p_xn, w_qkv, b_qkv, (float*)p_qkv,
        NTOK, 3 * HSZ, HSZ, 1.0f);

    // 3) attention
    const int smem = (AQ * APAD + AK * APAD + AK * APAD + AQ * APAD) * (int)sizeof(float);
    cudaFuncSetAttribute(attn_kernel, cudaFuncAttributeMaxDynamicSharedMemorySize, smem);
    attn_kernel<<<dim3(SEQ / AQ, NHEADS, BATCH), 256, smem>>>((float*)p_att);

    // 4) output projection: ([4096,1024] @ [1024,1024]^T + b) * 0.1
    sgemm_tn<<<dim3(HSZ / 128, NTOK / 128), 256>>>(
        (const float*)p_att, w_out, b_out, out,
        NTOK, HSZ, HSZ, 0.1f);
}

// round 4
// speedup vs baseline: 1.6059x; 1.3972x over previous
#include <cuda_runtime.h>
#include <cuda_bf16.h>
#include <math.h>
#include <stdint.h>

#define HSZ   1024
#define NHEADS 16
#define HDIM  64
#define BATCH 2
#define SEQ   2048
#define NTOK  (BATCH*SEQ)   /* 4096 */

// -------- scratch (allocation-free rule: __device__ globals) --------
__device__ float g_xn[(size_t)NTOK * HSZ];                 // 16 MB
__device__ float g_gate[NTOK];                             // 16 KB
__device__ float g_qkv[(size_t)NTOK * 3 * HSZ];            // 48 MB
__device__ float g_att[(size_t)NTOK * HSZ];                // 16 MB

// ============================================================
// Kernel 1: LayerNorm + entropy gate (one block per token)
// ============================================================
__global__ __launch_bounds__(256) void ln_gate_kernel(
    const float* __restrict__ x,
    const float* __restrict__ lng,
    const float* __restrict__ lnb,
    const float* __restrict__ w_ent,
    const float* __restrict__ b_ent)
{
    __shared__ float sbuf[8];
    const int t   = blockIdx.x;
    const int tid = threadIdx.x;
    const float* xr = x + (size_t)t * HSZ;

    float v[4];
    float s = 0.f;
#pragma unroll
    for (int r = 0; r < 4; r++) { v[r] = xr[tid + r * 256]; s += v[r]; }
#pragma unroll
    for (int off = 16; off; off >>= 1) s += __shfl_xor_sync(0xffffffffu, s, off);
    if ((tid & 31) == 0) sbuf[tid >> 5] = s;
    __syncthreads();
    float tot = 0.f;
#pragma unroll
    for (int i = 0; i < 8; i++) tot += sbuf[i];
    __syncthreads();
    const float mu = tot * (1.f / HSZ);

    float s2 = 0.f;
#pragma unroll
    for (int r = 0; r < 4; r++) { float d = v[r] - mu; s2 += d * d; }
#pragma unroll
    for (int off = 16; off; off >>= 1) s2 += __shfl_xor_sync(0xffffffffu, s2, off);
    if ((tid & 31) == 0) sbuf[tid >> 5] = s2;
    __syncthreads();
    float tot2 = 0.f;
#pragma unroll
    for (int i = 0; i < 8; i++) tot2 += sbuf[i];
    __syncthreads();
    const float rstd = rsqrtf(tot2 * (1.f / HSZ) + 1e-6f);

    float e = 0.f;
#pragma unroll
    for (int r = 0; r < 4; r++) {
        const int idx = tid + r * 256;
        const float xn = (v[r] - mu) * rstd * lng[idx] + lnb[idx];
        g_xn[(size_t)t * HSZ + idx] = xn;
        e += xn * w_ent[idx];
    }
#pragma unroll
    for (int off = 16; off; off >>= 1) e += __shfl_xor_sync(0xffffffffu, e, off);
    if ((tid & 31) == 0) sbuf[tid >> 5] = e;
    __syncthreads();
    if (tid == 0) {
        float et = 0.f;
#pragma unroll
        for (int i = 0; i < 8; i++) et += sbuf[i];
        float gt = 1.f / (1.f + __expf(-(et + b_ent[0])));
        g_gate[t] = fminf(fmaxf(gt, 0.1f), 2.0f);
    }
}

// ============================================================
// Kernel 2: mma.sync bf16x3 GEMM  C = alpha*(A @ Bw^T + bias)
// A:[M,K] rm, Bw:[N,K] rm. BM=BN=128, BK=32, 256 thr (8 warps, 64x32 each).
// fp32 split to bf16 hi/lo at fill; D = Ah*Bh + Ah*Bl + Al*Bh (fp32 acc).
// ============================================================
#define TSTR 40                       /* bf16 elems per smem row (32 + 8 pad) */
#define TILE_E (128 * TSTR)           /* 5120 bf16 per tile */
#define BUF_E  (4 * TILE_E)           /* Ah,Al,Bh,Bl per buffer */
#define G_SMEM (2 * BUF_E * 2)        /* bytes: 81920 */

struct alignas(8) B4 { __nv_bfloat16 v[4]; };

#define MMA_BF16(c, a, b) \
    asm volatile("mma.sync.aligned.m16n8k16.row.col.f32.bf16.bf16.f32 " \
        "{%0,%1,%2,%3}, {%4,%5,%6,%7}, {%8,%9}, {%0,%1,%2,%3};" \
        : "+f"((c)[0]), "+f"((c)[1]), "+f"((c)[2]), "+f"((c)[3]) \
        : "r"((a)[0]), "r"((a)[1]), "r"((a)[2]), "r"((a)[3]), \
          "r"((b)[0]), "r"((b)[1]))

__device__ __forceinline__ void split_store(__nv_bfloat16* hi, __nv_bfloat16* lo,
                                            int off, float4 a)
{
    B4 hb, lb;
    hb.v[0] = __float2bfloat16(a.x); lb.v[0] = __float2bfloat16(a.x - __bfloat162float(hb.v[0]));
    hb.v[1] = __float2bfloat16(a.y); lb.v[1] = __float2bfloat16(a.y - __bfloat162float(hb.v[1]));
    hb.v[2] = __float2bfloat16(a.z); lb.v[2] = __float2bfloat16(a.z - __bfloat162float(hb.v[2]));
    hb.v[3] = __float2bfloat16(a.w); lb.v[3] = __float2bfloat16(a.w - __bfloat162float(hb.v[3]));
    *(B4*)&hi[off] = hb;
    *(B4*)&lo[off] = lb;
}

__global__ __launch_bounds__(256, 1) void bf16x3_gemm(
    const float* __restrict__ A, const float* __restrict__ Bw,
    const float* __restrict__ bias, float* __restrict__ C,
    int M, int N, int K, float alpha)
{
    extern __shared__ __nv_bfloat16 sm[];
    const int tid  = threadIdx.x;
    const int wid  = tid >> 5;
    const int lane = tid & 31;
    const int g  = lane >> 2;         // 0..7
    const int tg = lane & 3;          // 0..3
    const int wm = (wid >> 2) * 64;   // 0 or 64
    const int wn = (wid & 3) * 32;    // 0,32,64,96
    const int m0 = blockIdx.y * 128, n0 = blockIdx.x * 128;

    const int lr  = tid >> 3;          // 0..31 base row per fill iter (x4)
    const int lc4 = tid & 7;           // float4 index within 8-per-row

    float acc[4][4][4];
#pragma unroll
    for (int mt = 0; mt < 4; mt++)
#pragma unroll
        for (int nt = 0; nt < 4; nt++)
#pragma unroll
            for (int q = 0; q < 4; q++) acc[mt][nt][q] = 0.f;

    const int NC = K >> 5;   // K/32 chunks
    float4 pa[4], pb[4];

    // ---- prologue: chunk 0 ----
#pragma unroll
    for (int i = 0; i < 4; i++) {
        const int r = lr + i * 32;
        pa[i] = *(const float4*)(A  + (size_t)(m0 + r) * K + (lc4 << 2));
        pb[i] = *(const float4*)(Bw + (size_t)(n0 + r) * K + (lc4 << 2));
    }
    {
        __nv_bfloat16* Ah = sm;
        __nv_bfloat16* Al = sm + TILE_E;
        __nv_bfloat16* Bh = sm + 2 * TILE_E;
        __nv_bfloat16* Bl = sm + 3 * TILE_E;
#pragma unroll
        for (int i = 0; i < 4; i++) {
            const int off = (lr + i * 32) * TSTR + (lc4 << 2);
            split_store(Ah, Al, off, pa[i]);
            split_store(Bh, Bl, off, pb[i]);
        }
    }
    __syncthreads();

    for (int c = 0; c < NC; c++) {
        const int cur = c & 1;
        if (c + 1 < NC) {
            const int k0 = (c + 1) << 5;
#pragma unroll
            for (int i = 0; i < 4; i++) {
                const int r = lr + i * 32;
                pa[i] = *(const float4*)(A  + (size_t)(m0 + r) * K + k0 + (lc4 << 2));
                pb[i] = *(const float4*)(Bw + (size_t)(n0 + r) * K + k0 + (lc4 << 2));
            }
        }

        const __nv_bfloat16* Ah = sm + cur * BUF_E;
        const __nv_bfloat16* Al = Ah + TILE_E;
        const __nv_bfloat16* Bh = Ah + 2 * TILE_E;
        const __nv_bfloat16* Bl = Ah + 3 * TILE_E;

#pragma unroll
        for (int kk = 0; kk < 32; kk += 16) {
            uint32_t ah[4][4], al[4][4], bh[4][2], bl[4][2];
#pragma unroll
            for (int mt = 0; mt < 4; mt++) {
                const int row = wm + mt * 16;
                const int o0 = (row + g) * TSTR + kk + tg * 2;
                const int o1 = (row + g + 8) * TSTR + kk + tg * 2;
                ah[mt][0] = *(const uint32_t*)&Ah[o0];
                ah[mt][1] = *(const uint32_t*)&Ah[o1];
                ah[mt][2] = *(const uint32_t*)&Ah[o0 + 8];
                ah[mt][3] = *(const uint32_t*)&Ah[o1 + 8];
                al[mt][0] = *(const uint32_t*)&Al[o0];
                al[mt][1] = *(const uint32_t*)&Al[o1];
                al[mt][2] = *(const uint32_t*)&Al[o0 + 8];
                al[mt][3] = *(const uint32_t*)&Al[o1 + 8];
            }
#pragma unroll
            for (int nt = 0; nt < 4; nt++) {
                const int ob = (wn + nt * 8 + g) * TSTR + kk + tg * 2;
                bh[nt][0] = *(const uint32_t*)&Bh[ob];
                bh[nt][1] = *(const uint32_t*)&Bh[ob + 8];
                bl[nt][0] = *(const uint32_t*)&Bl[ob];
                bl[nt][1] = *(const uint32_t*)&Bl[ob + 8];
            }
#pragma unroll
            for (int mt = 0; mt < 4; mt++)
#pragma unroll
                for (int nt = 0; nt < 4; nt++) {
                    MMA_BF16(acc[mt][nt], ah[mt], bh[nt]);
                    MMA_BF16(acc[mt][nt], ah[mt], bl[nt]);
                    MMA_BF16(acc[mt][nt], al[mt], bh[nt]);
                }
        }

        if (c + 1 < NC) {
            __nv_bfloat16* Ah2 = sm + ((c + 1) & 1) * BUF_E;
            __nv_bfloat16* Al2 = Ah2 + TILE_E;
            __nv_bfloat16* Bh2 = Ah2 + 2 * TILE_E;
            __nv_bfloat16* Bl2 = Ah2 + 3 * TILE_E;
#pragma unroll
            for (int i = 0; i < 4; i++) {
                const int off = (lr + i * 32) * TSTR + (lc4 << 2);
                split_store(Ah2, Al2, off, pa[i]);
                split_store(Bh2, Bl2, off, pb[i]);
            }
            __syncthreads();
        }
    }

    // epilogue
#pragma unroll
    for (int mt = 0; mt < 4; mt++) {
        const int row = m0 + wm + mt * 16 + g;
#pragma unroll
        for (int nt = 0; nt < 4; nt++) {
            const int col = n0 + wn + nt * 8 + tg * 2;
            const float b0 = bias[col], b1 = bias[col + 1];
            float2 o;
            o.x = alpha * (acc[mt][nt][0] + b0);
            o.y = alpha * (acc[mt][nt][1] + b1);
            *(float2*)(C + (size_t)row * N + col) = o;
            o.x = alpha * (acc[mt][nt][2] + b0);
            o.y = alpha * (acc[mt][nt][3] + b1);
            *(float2*)(C + (size_t)(row + 8) * N + col) = o;
        }
    }
}

// ============================================================
// Kernel 3: causal flash attention, temp=0.1, per-key gate
// 128q x 64k tiles, 256 threads, 8x4 per thread. (unchanged, fp32)
// ============================================================
#define AQ 128
#define AK 64
#define APAD 68

__global__ __launch_bounds__(256, 1) void attn_kernel(float* __restrict__ att)
{
    extern __shared__ float smf[];
    float* Qs = smf;                     // [128][68]
    float* Ks = Qs + AQ * APAD;          // [64][68]
    float* Vs = Ks + AK * APAD;          // [64][68]  (pre-gated)
    float* Ps = Vs + AK * APAD;          // [128][68]

    const int qt = gridDim.x - 1 - blockIdx.x;
    const int h = blockIdx.y, b = blockIdx.z;
    const int tid = threadIdx.x;
    const int tx = tid & 15, ty = tid >> 4;
    const int q0 = qt * AQ;
    const float sc = 1.25f;

#pragma unroll
    for (int r = 0; r < 8; r++) {
        const int idx = tid + r * 256;
        const int row = idx >> 4;
        const int d4  = (idx & 15) << 2;
        float4 qv = *(const float4*)&g_qkv[(size_t)(b * SEQ + q0 + row) * 3072 + h * 64 + d4];
        Qs[row * APAD + d4 + 0] = qv.x; Qs[row * APAD + d4 + 1] = qv.y;
        Qs[row * APAD + d4 + 2] = qv.z; Qs[row * APAD + d4 + 3] = qv.w;
    }

    float m_i[8], l_i[8], acc[8][4];
#pragma unroll
    for (int i = 0; i < 8; i++) {
        m_i[i] = -INFINITY; l_i[i] = 0.f;
#pragma unroll
        for (int j = 0; j < 4; j++) acc[i][j] = 0.f;
    }

    const int nkt = 2 * qt + 2;
    for (int kt = 0; kt < nkt; kt++) {
        const int k0 = kt * AK;
        __syncthreads();
#pragma unroll
        for (int r = 0; r < 4; r++) {
            const int idx = tid + r * 256;
            const int row = idx >> 4;
            const int d4  = (idx & 15) << 2;
            const size_t base = (size_t)(b * SEQ + k0 + row) * 3072 + h * 64 + d4;
            float4 kv = *(const float4*)&g_qkv[base + 1024];
            Ks[row * APAD + d4 + 0] = kv.x; Ks[row * APAD + d4 + 1] = kv.y;
            Ks[row * APAD + d4 + 2] = kv.z; Ks[row * APAD + d4 + 3] = kv.w;
            const float g = g_gate[b * SEQ + k0 + row];
            float4 vv = *(const float4*)&g_qkv[base + 2048];
            Vs[row * APAD + d4 + 0] = vv.x * g; Vs[row * APAD + d4 + 1] = vv.y * g;
            Vs[row * APAD + d4 + 2] = vv.z * g; Vs[row * APAD + d4 + 3] = vv.w * g;
        }
        __syncthreads();

        float s[8][4];
#pragma unroll
        for (int i = 0; i < 8; i++)
#pragma unroll
            for (int j = 0; j < 4; j++) s[i][j] = 0.f;

#pragma unroll 4
        for (int d = 0; d < 64; d += 4) {
            float4 kr[4];
#pragma unroll
            for (int j = 0; j < 4; j++)
                kr[j] = *(const float4*)&Ks[((tx << 2) + j) * APAD + d];
#pragma unroll
            for (int i = 0; i < 8; i++) {
                float4 q = *(const float4*)&Qs[((ty << 3) + i) * APAD + d];
#pragma unroll
                for (int j = 0; j < 4; j++) {
                    s[i][j] = fmaf(q.x, kr[j].x, s[i][j]);
                    s[i][j] = fmaf(q.y, kr[j].y, s[i][j]);
                    s[i][j] = fmaf(q.z, kr[j].z, s[i][j]);
                    s[i][j] = fmaf(q.w, kr[j].w, s[i][j]);
                }
            }
        }

        if (kt >= 2 * qt) {
#pragma unroll
            for (int i = 0; i < 8; i++) {
                const int gq = q0 + (ty << 3) + i;
#pragma unroll
                for (int j = 0; j < 4; j++) {
                    s[i][j] *= sc;
                    if ((k0 + (tx << 2) + j) > gq) s[i][j] = -INFINITY;
                }
            }
        } else {
#pragma unroll
            for (int i = 0; i < 8; i++)
#pragma unroll
                for (int j = 0; j < 4; j++) s[i][j] *= sc;
        }

#pragma unroll
        for (int i = 0; i < 8; i++) {
            float tm = fmaxf(fmaxf(s[i][0], s[i][1]), fmaxf(s[i][2], s[i][3]));
#pragma unroll
            for (int off = 1; off < 16; off <<= 1)
                tm = fmaxf(tm, __shfl_xor_sync(0xffffffffu, tm, off));
            const float nm = fmaxf(m_i[i], tm);
            const float al = __expf(m_i[i] - nm);
            float rs = 0.f;
#pragma unroll
            for (int j = 0; j < 4; j++) {
                const float p = __expf(s[i][j] - nm);
                s[i][j] = p;
                rs += p;
            }
#pragma unroll
            for (int off = 1; off < 16; off <<= 1)
                rs += __shfl_xor_sync(0xffffffffu, rs, off);
            l_i[i] = l_i[i] * al + rs;
            m_i[i] = nm;
#pragma unroll
            for (int j = 0; j < 4; j++) acc[i][j] *= al;
        }

#pragma unroll
        for (int i = 0; i < 8; i++) {
            float4 pv4;
            pv4.x = s[i][0]; pv4.y = s[i][1]; pv4.z = s[i][2]; pv4.w = s[i][3];
            *(float4*)&Ps[((ty << 3) + i) * APAD + (tx << 2)] = pv4;
        }
        __syncthreads();

#pragma unroll 4
        for (int kc = 0; kc < 64; kc += 4) {
            float4 vr[4];
#pragma unroll
            for (int jj = 0; jj < 4; jj++)
                vr[jj] = *(const float4*)&Vs[(kc + jj) * APAD + (tx << 2)];
#pragma unroll
            for (int i = 0; i < 8; i++) {
                float4 p = *(const float4*)&Ps[((ty << 3) + i) * APAD + kc];
                acc[i][0] = fmaf(p.x, vr[0].x, acc[i][0]);
                acc[i][0] = fmaf(p.y, vr[1].x, acc[i][0]);
                acc[i][0] = fmaf(p.z, vr[2].x, acc[i][0]);
                acc[i][0] = fmaf(p.w, vr[3].x, acc[i][0]);
                acc[i][1] = fmaf(p.x, vr[0].y, acc[i][1]);
                acc[i][1] = fmaf(p.y, vr[1].y, acc[i][1]);
                acc[i][1] = fmaf(p.z, vr[2].y, acc[i][1]);
                acc[i][1] = fmaf(p.w, vr[3].y, acc[i][1]);
                acc[i][2] = fmaf(p.x, vr[0].z, acc[i][2]);
                acc[i][2] = fmaf(p.y, vr[1].z, acc[i][2]);
                acc[i][2] = fmaf(p.z, vr[2].z, acc[i][2]);
                acc[i][2] = fmaf(p.w, vr[3].z, acc[i][2]);
                acc[i][3] = fmaf(p.x, vr[0].w, acc[i][3]);
                acc[i][3] = fmaf(p.y, vr[1].w, acc[i][3]);
                acc[i][3] = fmaf(p.z, vr[2].w, acc[i][3]);
                acc[i][3] = fmaf(p.w, vr[3].w, acc[i][3]);
            }
        }
    }

#pragma unroll
    for (int i = 0; i < 8; i++) {
        const float inv = 1.f / l_i[i];
        float4 o;
        o.x = acc[i][0] * inv; o.y = acc[i][1] * inv;
        o.z = acc[i][2] * inv; o.w = acc[i][3] * inv;
        *(float4*)&att[(size_t)(b * SEQ + q0 + (ty << 3) + i) * HSZ + h * 64 + (tx << 2)] = o;
    }
}

// ============================================================
// host launcher
// ============================================================
extern "C" void kernel_launch(void* const* d_in, const int* in_sizes, int n_in,
                              void* d_out, int out_size)
{
    const float* x     = (const float*)d_in[0];
    const float* ln_g  = (const float*)d_in[1];
    const float* ln_b  = (const float*)d_in[2];
    const float* w_qkv = (const float*)d_in[3];
    const float* b_qkv = (const float*)d_in[4];
    const float* w_ent = (const float*)d_in[5];
    const float* b_ent = (const float*)d_in[6];
    const float* w_out = (const float*)d_in[7];
    const float* b_out = (const float*)d_in[8];
    float* out = (float*)d_out;

    void *p_xn, *p_qkv, *p_att;
    cudaGetSymbolAddress(&p_xn,  g_xn);
    cudaGetSymbolAddress(&p_qkv, g_qkv);
    cudaGetSymbolAddress(&p_att, g_att);

    cudaFuncSetAttribute(bf16x3_gemm, cudaFuncAttributeMaxDynamicSharedMemorySize, G_SMEM);

    // 1) LN + entropy gate
    ln_gate_kernel<<<NTOK, 256>>>(x, ln_g, ln_b, w_ent, b_ent);

    // 2) QKV projection: [4096,1024] @ [3072,1024]^T -> [4096,3072]
    bf16x3_gemm<<<dim3(3 * HSZ / 128, NTOK / 128), 256, G_SMEM>>>(
        (const float*)p_xn, w_qkv, b_qkv, (float*)p_qkv,
        NTOK, 3 * HSZ, HSZ, 1.0f);

    // 3) attention
    const int asmem = (AQ * APAD + AK * APAD + AK * APAD + AQ * APAD) * (int)sizeof(float);
    cudaFuncSetAttribute(attn_kernel, cudaFuncAttributeMaxDynamicSharedMemorySize, asmem);
    attn_kernel<<<dim3(SEQ / AQ, NHEADS, BATCH), 256, asmem>>>((float*)p_att);

    // 4) output projection: ([4096,1024] @ [1024,1024]^T + b) * 0.1
    bf16x3_gemm<<<dim3(HSZ / 128, NTOK / 128), 256, G_SMEM>>>(
        (const float*)p_att, w_out, b_out, out,
        NTOK, HSZ, HSZ, 0.1f);
}

// round 8
// speedup vs baseline: 2.6828x; 1.6706x over previous
#include <cuda_runtime.h>
#include <cuda_bf16.h>
#include <math.h>
#include <stdint.h>

#define HSZ   1024
#define NHEADS 16
#define HDIM  64
#define BATCH 2
#define SEQ   2048
#define NTOK  (BATCH*SEQ)   /* 4096 */

// -------- scratch (allocation-free rule: __device__ globals) --------
__device__ float g_xn[(size_t)NTOK * HSZ];                 // 16 MB
__device__ float g_gate[NTOK];                             // 16 KB
__device__ float g_qkv[(size_t)NTOK * 3 * HSZ];            // 48 MB
__device__ float g_att[(size_t)NTOK * HSZ];                // 16 MB

struct alignas(8) B4 { __nv_bfloat16 v[4]; };

#define MMA_BF16(c, a, b) \
    asm volatile("mma.sync.aligned.m16n8k16.row.col.f32.bf16.bf16.f32 " \
        "{%0,%1,%2,%3}, {%4,%5,%6,%7}, {%8,%9}, {%0,%1,%2,%3};" \
        : "+f"((c)[0]), "+f"((c)[1]), "+f"((c)[2]), "+f"((c)[3]) \
        : "r"((a)[0]), "r"((a)[1]), "r"((a)[2]), "r"((a)[3]), \
          "r"((b)[0]), "r"((b)[1]))

__device__ __forceinline__ uint32_t pack2bf(float lo, float hi) {
    __nv_bfloat162 t = __floats2bfloat162_rn(lo, hi);
    return *(uint32_t*)&t;
}

// ============================================================
// Kernel 1: LayerNorm + entropy gate (one block per token)
// ============================================================
__global__ __launch_bounds__(256) void ln_gate_kernel(
    const float* __restrict__ x,
    const float* __restrict__ lng,
    const float* __restrict__ lnb,
    const float* __restrict__ w_ent,
    const float* __restrict__ b_ent)
{
    __shared__ float sbuf[8];
    const int t   = blockIdx.x;
    const int tid = threadIdx.x;
    const float* xr = x + (size_t)t * HSZ;

    float v[4];
    float s = 0.f;
#pragma unroll
    for (int r = 0; r < 4; r++) { v[r] = xr[tid + r * 256]; s += v[r]; }
#pragma unroll
    for (int off = 16; off; off >>= 1) s += __shfl_xor_sync(0xffffffffu, s, off);
    if ((tid & 31) == 0) sbuf[tid >> 5] = s;
    __syncthreads();
    float tot = 0.f;
#pragma unroll
    for (int i = 0; i < 8; i++) tot += sbuf[i];
    __syncthreads();
    const float mu = tot * (1.f / HSZ);

    float s2 = 0.f;
#pragma unroll
    for (int r = 0; r < 4; r++) { float d = v[r] - mu; s2 += d * d; }
#pragma unroll
    for (int off = 16; off; off >>= 1) s2 += __shfl_xor_sync(0xffffffffu, s2, off);
    if ((tid & 31) == 0) sbuf[tid >> 5] = s2;
    __syncthreads();
    float tot2 = 0.f;
#pragma unroll
    for (int i = 0; i < 8; i++) tot2 += sbuf[i];
    __syncthreads();
    const float rstd = rsqrtf(tot2 * (1.f / HSZ) + 1e-6f);

    float e = 0.f;
#pragma unroll
    for (int r = 0; r < 4; r++) {
        const int idx = tid + r * 256;
        const float xn = (v[r] - mu) * rstd * lng[idx] + lnb[idx];
        g_xn[(size_t)t * HSZ + idx] = xn;
        e += xn * w_ent[idx];
    }
#pragma unroll
    for (int off = 16; off; off >>= 1) e += __shfl_xor_sync(0xffffffffu, e, off);
    if ((tid & 31) == 0) sbuf[tid >> 5] = e;
    __syncthreads();
    if (tid == 0) {
        float et = 0.f;
#pragma unroll
        for (int i = 0; i < 8; i++) et += sbuf[i];
        float gt = 1.f / (1.f + __expf(-(et + b_ent[0])));
        g_gate[t] = fminf(fmaxf(gt, 0.1f), 2.0f);
    }
}

// ============================================================
// Kernel 2: mma.sync bf16x3 GEMM  C = alpha*(A @ Bw^T + bias)
// (unchanged — known good)
// ============================================================
#define TSTR 40
#define TILE_E (128 * TSTR)
#define BUF_E  (4 * TILE_E)
#define G_SMEM (2 * BUF_E * 2)

__device__ __forceinline__ void split_store(__nv_bfloat16* hi, __nv_bfloat16* lo,
                                            int off, float4 a)
{
    B4 hb, lb;
    hb.v[0] = __float2bfloat16(a.x); lb.v[0] = __float2bfloat16(a.x - __bfloat162float(hb.v[0]));
    hb.v[1] = __float2bfloat16(a.y); lb.v[1] = __float2bfloat16(a.y - __bfloat162float(hb.v[1]));
    hb.v[2] = __float2bfloat16(a.z); lb.v[2] = __float2bfloat16(a.z - __bfloat162float(hb.v[2]));
    hb.v[3] = __float2bfloat16(a.w); lb.v[3] = __float2bfloat16(a.w - __bfloat162float(hb.v[3]));
    *(B4*)&hi[off] = hb;
    *(B4*)&lo[off] = lb;
}

__global__ __launch_bounds__(256, 1) void bf16x3_gemm(
    const float* __restrict__ A, const float* __restrict__ Bw,
    const float* __restrict__ bias, float* __restrict__ C,
    int M, int N, int K, float alpha)
{
    extern __shared__ __nv_bfloat16 sm[];
    const int tid  = threadIdx.x;
    const int wid  = tid >> 5;
    const int lane = tid & 31;
    const int g  = lane >> 2;
    const int tg = lane & 3;
    const int wm = (wid >> 2) * 64;
    const int wn = (wid & 3) * 32;
    const int m0 = blockIdx.y * 128, n0 = blockIdx.x * 128;

    const int lr  = tid >> 3;
    const int lc4 = tid & 7;

    float acc[4][4][4];
#pragma unroll
    for (int mt = 0; mt < 4; mt++)
#pragma unroll
        for (int nt = 0; nt < 4; nt++)
#pragma unroll
            for (int q = 0; q < 4; q++) acc[mt][nt][q] = 0.f;

    const int NC = K >> 5;
    float4 pa[4], pb[4];

#pragma unroll
    for (int i = 0; i < 4; i++) {
        const int r = lr + i * 32;
        pa[i] = *(const float4*)(A  + (size_t)(m0 + r) * K + (lc4 << 2));
        pb[i] = *(const float4*)(Bw + (size_t)(n0 + r) * K + (lc4 << 2));
    }
    {
        __nv_bfloat16* Ah = sm;
        __nv_bfloat16* Al = sm + TILE_E;
        __nv_bfloat16* Bh = sm + 2 * TILE_E;
        __nv_bfloat16* Bl = sm + 3 * TILE_E;
#pragma unroll
        for (int i = 0; i < 4; i++) {
            const int off = (lr + i * 32) * TSTR + (lc4 << 2);
            split_store(Ah, Al, off, pa[i]);
            split_store(Bh, Bl, off, pb[i]);
        }
    }
    __syncthreads();

    for (int c = 0; c < NC; c++) {
        const int cur = c & 1;
        if (c + 1 < NC) {
            const int k0 = (c + 1) << 5;
#pragma unroll
            for (int i = 0; i < 4; i++) {
                const int r = lr + i * 32;
                pa[i] = *(const float4*)(A  + (size_t)(m0 + r) * K + k0 + (lc4 << 2));
                pb[i] = *(const float4*)(Bw + (size_t)(n0 + r) * K + k0 + (lc4 << 2));
            }
        }

        const __nv_bfloat16* Ah = sm + cur * BUF_E;
        const __nv_bfloat16* Al = Ah + TILE_E;
        const __nv_bfloat16* Bh = Ah + 2 * TILE_E;
        const __nv_bfloat16* Bl = Ah + 3 * TILE_E;

#pragma unroll
        for (int kk = 0; kk < 32; kk += 16) {
            uint32_t ah[4][4], al[4][4], bh[4][2], bl[4][2];
#pragma unroll
            for (int mt = 0; mt < 4; mt++) {
                const int row = wm + mt * 16;
                const int o0 = (row + g) * TSTR + kk + tg * 2;
                const int o1 = (row + g + 8) * TSTR + kk + tg * 2;
                ah[mt][0] = *(const uint32_t*)&Ah[o0];
                ah[mt][1] = *(const uint32_t*)&Ah[o1];
                ah[mt][2] = *(const uint32_t*)&Ah[o0 + 8];
                ah[mt][3] = *(const uint32_t*)&Ah[o1 + 8];
                al[mt][0] = *(const uint32_t*)&Al[o0];
                al[mt][1] = *(const uint32_t*)&Al[o1];
                al[mt][2] = *(const uint32_t*)&Al[o0 + 8];
                al[mt][3] = *(const uint32_t*)&Al[o1 + 8];
            }
#pragma unroll
            for (int nt = 0; nt < 4; nt++) {
                const int ob = (wn + nt * 8 + g) * TSTR + kk + tg * 2;
                bh[nt][0] = *(const uint32_t*)&Bh[ob];
                bh[nt][1] = *(const uint32_t*)&Bh[ob + 8];
                bl[nt][0] = *(const uint32_t*)&Bl[ob];
                bl[nt][1] = *(const uint32_t*)&Bl[ob + 8];
            }
#pragma unroll
            for (int mt = 0; mt < 4; mt++)
#pragma unroll
                for (int nt = 0; nt < 4; nt++) {
                    MMA_BF16(acc[mt][nt], ah[mt], bh[nt]);
                    MMA_BF16(acc[mt][nt], ah[mt], bl[nt]);
                    MMA_BF16(acc[mt][nt], al[mt], bh[nt]);
                }
        }

        if (c + 1 < NC) {
            __nv_bfloat16* Ah2 = sm + ((c + 1) & 1) * BUF_E;
            __nv_bfloat16* Al2 = Ah2 + TILE_E;
            __nv_bfloat16* Bh2 = Ah2 + 2 * TILE_E;
            __nv_bfloat16* Bl2 = Ah2 + 3 * TILE_E;
#pragma unroll
            for (int i = 0; i < 4; i++) {
                const int off = (lr + i * 32) * TSTR + (lc4 << 2);
                split_store(Ah2, Al2, off, pa[i]);
                split_store(Bh2, Bl2, off, pb[i]);
            }
            __syncthreads();
        }
    }

#pragma unroll
    for (int mt = 0; mt < 4; mt++) {
        const int row = m0 + wm + mt * 16 + g;
#pragma unroll
        for (int nt = 0; nt < 4; nt++) {
            const int col = n0 + wn + nt * 8 + tg * 2;
            const float b0 = bias[col], b1 = bias[col + 1];
            float2 o;
            o.x = alpha * (acc[mt][nt][0] + b0);
            o.y = alpha * (acc[mt][nt][1] + b1);
            *(float2*)(C + (size_t)row * N + col) = o;
            o.x = alpha * (acc[mt][nt][2] + b0);
            o.y = alpha * (acc[mt][nt][3] + b1);
            *(float2*)(C + (size_t)(row + 8) * N + col) = o;
        }
    }
}

// ============================================================
// Kernel 3: mma.sync causal flash attention, temp=0.1, key gate
// 128q x 64k tiles, 8 warps x 16 q-rows.
// QK^T = bf16x3 (Qh/Ql x Kh/Kl); PV = bf16x3 (Ph/Pl x Vh/Vl).
// ============================================================
#define KSTR 72
#define VSTR 72
#define ATT_SMEM (4 * 64 * 72 * 2)   /* 36864 B: Kh,Kl,Vh,Vl; Q staging reuses */

__global__ __launch_bounds__(256, 1) void attn_mma(float* __restrict__ att)
{
    extern __shared__ __nv_bfloat16 sb[];
    __nv_bfloat16* Kh = sb;                        // [64][72]
    __nv_bfloat16* Kl = sb + 64 * KSTR;            // [64][72]
    __nv_bfloat16* Vh = sb + 2 * 64 * KSTR;        // [64 d][72 keys], gated hi
    __nv_bfloat16* Vl = sb + 3 * 64 * KSTR;        // [64 d][72 keys], gated lo

    const int qt  = gridDim.x - 1 - blockIdx.x;
    const int h   = blockIdx.y, b = blockIdx.z;
    const int tid = threadIdx.x;
    const int wid = tid >> 5;
    const int lane = tid & 31;
    const int gi = lane >> 2;       // row within 8-group
    const int tg = lane & 3;        // col pair selector
    const int q0 = qt * 128;
    const float scl = 1.25f;        // (1/sqrt(64))/0.1

    // ---- stage Q (hi/lo bf16) into smem, then load fragments ----
    {
        __nv_bfloat16* Qh = sb;                  // [128][72]
        __nv_bfloat16* Ql = sb + 128 * KSTR;
#pragma unroll
        for (int i = 0; i < 8; i++) {
            const int idx = tid + i * 256;
            const int row = idx >> 4, c4 = idx & 15;
            float4 q = *(const float4*)&g_qkv[(size_t)(b * SEQ + q0 + row) * 3072 + h * 64 + (c4 << 2)];
            split_store(Qh, Ql, row * KSTR + (c4 << 2), q);
        }
    }
    __syncthreads();

    uint32_t qh[4][4], ql[4][4];
    {
        const __nv_bfloat16* Qh = sb;
        const __nv_bfloat16* Ql = sb + 128 * KSTR;
        const int r0 = 16 * wid + gi;
#pragma unroll
        for (int ds = 0; ds < 4; ds++) {
            const int k = ds * 16 + tg * 2;
            qh[ds][0] = *(const uint32_t*)&Qh[r0 * KSTR + k];
            qh[ds][1] = *(const uint32_t*)&Qh[(r0 + 8) * KSTR + k];
            qh[ds][2] = *(const uint32_t*)&Qh[r0 * KSTR + k + 8];
            qh[ds][3] = *(const uint32_t*)&Qh[(r0 + 8) * KSTR + k + 8];
            ql[ds][0] = *(const uint32_t*)&Ql[r0 * KSTR + k];
            ql[ds][1] = *(const uint32_t*)&Ql[(r0 + 8) * KSTR + k];
            ql[ds][2] = *(const uint32_t*)&Ql[r0 * KSTR + k + 8];
            ql[ds][3] = *(const uint32_t*)&Ql[(r0 + 8) * KSTR + k + 8];
        }
    }
    __syncthreads();   // fragments loaded; smem free for K/V

    float m0v = -INFINITY, m1v = -INFINITY, l0v = 0.f, l1v = 0.f;
    float acc_o[8][4];
#pragma unroll
    for (int nt = 0; nt < 8; nt++)
#pragma unroll
        for (int q = 0; q < 4; q++) acc_o[nt][q] = 0.f;

    const int row0 = q0 + 16 * wid + gi;
    const int row1 = row0 + 8;
    const int rmax = q0 + 16 * wid + 15;
    const int nkt = 2 * qt + 2;

    for (int kt = 0; kt < nkt; kt++) {
        const int k0 = kt * 64;
        // ---- cooperative K/V fill (V gated in fp32 then split hi/lo) ----
#pragma unroll
        for (int i = 0; i < 4; i++) {
            const int idx = tid + i * 256;
            const int key = idx >> 4, c4 = idx & 15;
            const size_t base = (size_t)(b * SEQ + k0 + key) * 3072 + h * 64 + (c4 << 2);
            float4 kv = *(const float4*)&g_qkv[base + 1024];
            split_store(Kh, Kl, key * KSTR + (c4 << 2), kv);
            const float g = g_gate[b * SEQ + k0 + key];
            float4 vv = *(const float4*)&g_qkv[base + 2048];
            const float v0 = vv.x * g, v1 = vv.y * g, v2 = vv.z * g, v3 = vv.w * g;
            __nv_bfloat16 h0 = __float2bfloat16(v0);
            __nv_bfloat16 h1 = __float2bfloat16(v1);
            __nv_bfloat16 h2 = __float2bfloat16(v2);
            __nv_bfloat16 h3 = __float2bfloat16(v3);
            const int d0 = c4 << 2;
            Vh[(d0 + 0) * VSTR + key] = h0;
            Vh[(d0 + 1) * VSTR + key] = h1;
            Vh[(d0 + 2) * VSTR + key] = h2;
            Vh[(d0 + 3) * VSTR + key] = h3;
            Vl[(d0 + 0) * VSTR + key] = __float2bfloat16(v0 - __bfloat162float(h0));
            Vl[(d0 + 1) * VSTR + key] = __float2bfloat16(v1 - __bfloat162float(h1));
            Vl[(d0 + 2) * VSTR + key] = __float2bfloat16(v2 - __bfloat162float(h2));
            Vl[(d0 + 3) * VSTR + key] = __float2bfloat16(v3 - __bfloat162float(h3));
        }
        __syncthreads();

        if (k0 <= rmax) {
            // ---- QK^T (bf16x3) ----
            float s[8][4];
#pragma unroll
            for (int nt = 0; nt < 8; nt++)
#pragma unroll
                for (int q = 0; q < 4; q++) s[nt][q] = 0.f;

#pragma unroll
            for (int ds = 0; ds < 4; ds++) {
                const int kk = ds * 16 + tg * 2;
#pragma unroll
                for (int nt = 0; nt < 8; nt++) {
                    uint32_t bh[2], bl[2];
                    const int o = (nt * 8 + gi) * KSTR + kk;
                    bh[0] = *(const uint32_t*)&Kh[o];
                    bh[1] = *(const uint32_t*)&Kh[o + 8];
                    bl[0] = *(const uint32_t*)&Kl[o];
                    bl[1] = *(const uint32_t*)&Kl[o + 8];
                    MMA_BF16(s[nt], qh[ds], bh);
                    MMA_BF16(s[nt], qh[ds], bl);
                    MMA_BF16(s[nt], ql[ds], bh);
                }
            }

            // ---- scale + causal mask ----
#pragma unroll
            for (int nt = 0; nt < 8; nt++)
#pragma unroll
                for (int q = 0; q < 4; q++) s[nt][q] *= scl;
            if (kt >= 2 * qt) {
#pragma unroll
                for (int nt = 0; nt < 8; nt++) {
                    const int c0 = k0 + nt * 8 + tg * 2;
                    if (c0     > row0) s[nt][0] = -INFINITY;
                    if (c0 + 1 > row0) s[nt][1] = -INFINITY;
                    if (c0     > row1) s[nt][2] = -INFINITY;
                    if (c0 + 1 > row1) s[nt][3] = -INFINITY;
                }
            }

            // ---- online softmax (rows reduced over quad lanes) ----
            float mx0 = -INFINITY, mx1 = -INFINITY;
#pragma unroll
            for (int nt = 0; nt < 8; nt++) {
                mx0 = fmaxf(mx0, fmaxf(s[nt][0], s[nt][1]));
                mx1 = fmaxf(mx1, fmaxf(s[nt][2], s[nt][3]));
            }
            mx0 = fmaxf(mx0, __shfl_xor_sync(0xffffffffu, mx0, 1));
            mx0 = fmaxf(mx0, __shfl_xor_sync(0xffffffffu, mx0, 2));
            mx1 = fmaxf(mx1, __shfl_xor_sync(0xffffffffu, mx1, 1));
            mx1 = fmaxf(mx1, __shfl_xor_sync(0xffffffffu, mx1, 2));

            const float nm0 = fmaxf(m0v, mx0);
            const float nm1 = fmaxf(m1v, mx1);
            const float al0 = __expf(m0v - nm0);
            const float al1 = __expf(m1v - nm1);
            float rs0 = 0.f, rs1 = 0.f;
#pragma unroll
            for (int nt = 0; nt < 8; nt++) {
                s[nt][0] = __expf(s[nt][0] - nm0);
                s[nt][1] = __expf(s[nt][1] - nm0);
                s[nt][2] = __expf(s[nt][2] - nm1);
                s[nt][3] = __expf(s[nt][3] - nm1);
                rs0 += s[nt][0] + s[nt][1];
                rs1 += s[nt][2] + s[nt][3];
            }
            rs0 += __shfl_xor_sync(0xffffffffu, rs0, 1);
            rs0 += __shfl_xor_sync(0xffffffffu, rs0, 2);
            rs1 += __shfl_xor_sync(0xffffffffu, rs1, 1);
            rs1 += __shfl_xor_sync(0xffffffffu, rs1, 2);
            l0v = l0v * al0 + rs0;
            l1v = l1v * al1 + rs1;
            m0v = nm0; m1v = nm1;
#pragma unroll
            for (int nt = 0; nt < 8; nt++) {
                acc_o[nt][0] *= al0; acc_o[nt][1] *= al0;
                acc_o[nt][2] *= al1; acc_o[nt][3] *= al1;
            }

            // ---- PV (bf16x3): P split hi/lo in-register; V hi/lo in smem ----
#pragma unroll
            for (int s4 = 0; s4 < 4; s4++) {
                uint32_t pa[4], pl[4];
                {
                    const float p00 = s[2 * s4][0],     p01 = s[2 * s4][1];
                    const float p02 = s[2 * s4][2],     p03 = s[2 * s4][3];
                    const float p10 = s[2 * s4 + 1][0], p11 = s[2 * s4 + 1][1];
                    const float p12 = s[2 * s4 + 1][2], p13 = s[2 * s4 + 1][3];
                    pa[0] = pack2bf(p00, p01);
                    pa[1] = pack2bf(p02, p03);
                    pa[2] = pack2bf(p10, p11);
                    pa[3] = pack2bf(p12, p13);
                    __nv_bfloat162* ph;
                    ph = (__nv_bfloat162*)&pa[0];
                    pl[0] = pack2bf(p00 - __bfloat162float(ph->x), p01 - __bfloat162float(ph->y));
                    ph = (__nv_bfloat162*)&pa[1];
                    pl[1] = pack2bf(p02 - __bfloat162float(ph->x), p03 - __bfloat162float(ph->y));
                    ph = (__nv_bfloat162*)&pa[2];
                    pl[2] = pack2bf(p10 - __bfloat162float(ph->x), p11 - __bfloat162float(ph->y));
                    ph = (__nv_bfloat162*)&pa[3];
                    pl[3] = pack2bf(p12 - __bfloat162float(ph->x), p13 - __bfloat162float(ph->y));
                }
                const int kk = s4 * 16 + tg * 2;
#pragma unroll
                for (int nt = 0; nt < 8; nt++) {
                    uint32_t bvh[2], bvl[2];
                    const int o = (nt * 8 + gi) * VSTR + kk;
                    bvh[0] = *(const uint32_t*)&Vh[o];
                    bvh[1] = *(const uint32_t*)&Vh[o + 8];
                    bvl[0] = *(const uint32_t*)&Vl[o];
                    bvl[1] = *(const uint32_t*)&Vl[o + 8];
                    MMA_BF16(acc_o[nt], pa, bvh);
                    MMA_BF16(acc_o[nt], pa, bvl);
                    MMA_BF16(acc_o[nt], pl, bvh);
                }
            }
        }
        __syncthreads();   // tile consumed before next fill
    }

    // ---- epilogue ----
    const float inv0 = 1.f / l0v;
    const float inv1 = 1.f / l1v;
#pragma unroll
    for (int nt = 0; nt < 8; nt++) {
        const int col = h * 64 + nt * 8 + tg * 2;
        float2 o;
        o.x = acc_o[nt][0] * inv0; o.y = acc_o[nt][1] * inv0;
        *(float2*)&att[(size_t)(b * SEQ + row0) * HSZ + col] = o;
        o.x = acc_o[nt][2] * inv1; o.y = acc_o[nt][3] * inv1;
        *(float2*)&att[(size_t)(b * SEQ + row1) * HSZ + col] = o;
    }
}

// ============================================================
// host launcher
// ============================================================
extern "C" void kernel_launch(void* const* d_in, const int* in_sizes, int n_in,
                              void* d_out, int out_size)
{
    const float* x     = (const float*)d_in[0];
    const float* ln_g  = (const float*)d_in[1];
    const float* ln_b  = (const float*)d_in[2];
    const float* w_qkv = (const float*)d_in[3];
    const float* b_qkv = (const float*)d_in[4];
    const float* w_ent = (const float*)d_in[5];
    const float* b_ent = (const float*)d_in[6];
    const float* w_out = (const float*)d_in[7];
    const float* b_out = (const float*)d_in[8];
    float* out = (float*)d_out;

    void *p_xn, *p_qkv, *p_att;
    cudaGetSymbolAddress(&p_xn,  g_xn);
    cudaGetSymbolAddress(&p_qkv, g_qkv);
    cudaGetSymbolAddress(&p_att, g_att);

    cudaFuncSetAttribute(bf16x3_gemm, cudaFuncAttributeMaxDynamicSharedMemorySize, G_SMEM);
    cudaFuncSetAttribute(attn_mma, cudaFuncAttributeMaxDynamicSharedMemorySize, ATT_SMEM);

    // 1) LN + entropy gate
    ln_gate_kernel<<<NTOK, 256>>>(x, ln_g, ln_b, w_ent, b_ent);

    // 2) QKV projection: [4096,1024] @ [3072,1024]^T -> [4096,3072]
    bf16x3_gemm<<<dim3(3 * HSZ / 128, NTOK / 128), 256, G_SMEM>>>(
        (const float*)p_xn, w_qkv, b_qkv, (float*)p_qkv,
        NTOK, 3 * HSZ, HSZ, 1.0f);

    // 3) attention (mma.sync, fully error-compensated)
    attn_mma<<<dim3(SEQ / 128, NHEADS, BATCH), 256, ATT_SMEM>>>((float*)p_att);

    // 4) output projection: ([4096,1024] @ [1024,1024]^T + b) * 0.1
    bf16x3_gemm<<<dim3(HSZ / 128, NTOK / 128), 256, G_SMEM>>>(
        (const float*)p_att, w_out, b_out, out,
        NTOK, HSZ, HSZ, 0.1f);
}

// round 14
// speedup vs baseline: 2.8514x; 1.0629x over previous
#include <cuda_runtime.h>
#include <cuda_bf16.h>
#include <math.h>
#include <stdint.h>

#define HSZ   1024
#define NHEADS 16
#define HDIM  64
#define BATCH 2
#define SEQ   2048
#define NTOK  (BATCH*SEQ)   /* 4096 */

// -------- scratch (allocation-free rule: __device__ globals) --------
__device__ __nv_bfloat16 g_xh[(size_t)NTOK * HSZ];
__device__ __nv_bfloat16 g_xl[(size_t)NTOK * HSZ];
__device__ float         g_gate[NTOK];
__device__ __nv_bfloat16 g_wqh[(size_t)3 * HSZ * HSZ];
__device__ __nv_bfloat16 g_wql[(size_t)3 * HSZ * HSZ];
__device__ __nv_bfloat16 g_woh[(size_t)HSZ * HSZ];
__device__ __nv_bfloat16 g_wol[(size_t)HSZ * HSZ];
__device__ __nv_bfloat16 g_qkvh[(size_t)NTOK * 3 * HSZ];
__device__ __nv_bfloat16 g_qkvl[(size_t)NTOK * 3 * HSZ];
__device__ __nv_bfloat16 g_atth[(size_t)NTOK * HSZ];
__device__ __nv_bfloat16 g_attl[(size_t)NTOK * HSZ];

#define MMA_BF16(c, a, b) \
    asm volatile("mma.sync.aligned.m16n8k16.row.col.f32.bf16.bf16.f32 " \
        "{%0,%1,%2,%3}, {%4,%5,%6,%7}, {%8,%9}, {%0,%1,%2,%3};" \
        : "+f"((c)[0]), "+f"((c)[1]), "+f"((c)[2]), "+f"((c)[3]) \
        : "r"((a)[0]), "r"((a)[1]), "r"((a)[2]), "r"((a)[3]), \
          "r"((b)[0]), "r"((b)[1]))

__device__ __forceinline__ uint32_t pack2bf(float a, float b) {
    __nv_bfloat162 t = __floats2bfloat162_rn(a, b);
    return *(uint32_t*)&t;
}

// ============================================================
// Kernel 0: fp32 -> bf16 hi/lo splitter (weights)
// ============================================================
__global__ __launch_bounds__(256) void wsplit(
    const float* __restrict__ w, __nv_bfloat16* __restrict__ wh,
    __nv_bfloat16* __restrict__ wl, int n4)
{
    const int i = blockIdx.x * 256 + threadIdx.x;
    if (i >= n4) return;
    float4 a = ((const float4*)w)[i];
    __nv_bfloat16 h0 = __float2bfloat16(a.x);
    __nv_bfloat16 h1 = __float2bfloat16(a.y);
    __nv_bfloat16 h2 = __float2bfloat16(a.z);
    __nv_bfloat16 h3 = __float2bfloat16(a.w);
    *(uint32_t*)&wh[i * 4 + 0] = pack2bf(__bfloat162float(h0), __bfloat162float(h1));
    *(uint32_t*)&wh[i * 4 + 2] = pack2bf(__bfloat162float(h2), __bfloat162float(h3));
    *(uint32_t*)&wl[i * 4 + 0] = pack2bf(a.x - __bfloat162float(h0), a.y - __bfloat162float(h1));
    *(uint32_t*)&wl[i * 4 + 2] = pack2bf(a.z - __bfloat162float(h2), a.w - __bfloat162float(h3));
}

// ============================================================
// Kernel 1: LayerNorm + entropy gate; writes xn as bf16 hi/lo
// ============================================================
__global__ __launch_bounds__(256) void ln_gate_kernel(
    const float* __restrict__ x,
    const float* __restrict__ lng,
    const float* __restrict__ lnb,
    const float* __restrict__ w_ent,
    const float* __restrict__ b_ent)
{
    __shared__ float sbuf[8];
    const int t   = blockIdx.x;
    const int tid = threadIdx.x;
    const float* xr = x + (size_t)t * HSZ;

    float4 v = ((const float4*)xr)[tid];
    float s = v.x + v.y + v.z + v.w;
#pragma unroll
    for (int off = 16; off; off >>= 1) s += __shfl_xor_sync(0xffffffffu, s, off);
    if ((tid & 31) == 0) sbuf[tid >> 5] = s;
    __syncthreads();
    float tot = 0.f;
#pragma unroll
    for (int i = 0; i < 8; i++) tot += sbuf[i];
    __syncthreads();
    const float mu = tot * (1.f / HSZ);

    float d0 = v.x - mu, d1 = v.y - mu, d2 = v.z - mu, d3 = v.w - mu;
    float s2 = d0 * d0 + d1 * d1 + d2 * d2 + d3 * d3;
#pragma unroll
    for (int off = 16; off; off >>= 1) s2 += __shfl_xor_sync(0xffffffffu, s2, off);
    if ((tid & 31) == 0) sbuf[tid >> 5] = s2;
    __syncthreads();
    float tot2 = 0.f;
#pragma unroll
    for (int i = 0; i < 8; i++) tot2 += sbuf[i];
    __syncthreads();
    const float rstd = rsqrtf(tot2 * (1.f / HSZ) + 1e-6f);

    float4 lg = ((const float4*)lng)[tid];
    float4 lb = ((const float4*)lnb)[tid];
    float4 we = ((const float4*)w_ent)[tid];
    const float xn0 = d0 * rstd * lg.x + lb.x;
    const float xn1 = d1 * rstd * lg.y + lb.y;
    const float xn2 = d2 * rstd * lg.z + lb.z;
    const float xn3 = d3 * rstd * lg.w + lb.w;

    __nv_bfloat16 h0 = __float2bfloat16(xn0);
    __nv_bfloat16 h1 = __float2bfloat16(xn1);
    __nv_bfloat16 h2 = __float2bfloat16(xn2);
    __nv_bfloat16 h3 = __float2bfloat16(xn3);
    const size_t o = (size_t)t * HSZ + tid * 4;
    *(uint32_t*)&g_xh[o + 0] = pack2bf(__bfloat162float(h0), __bfloat162float(h1));
    *(uint32_t*)&g_xh[o + 2] = pack2bf(__bfloat162float(h2), __bfloat162float(h3));
    *(uint32_t*)&g_xl[o + 0] = pack2bf(xn0 - __bfloat162float(h0), xn1 - __bfloat162float(h1));
    *(uint32_t*)&g_xl[o + 2] = pack2bf(xn2 - __bfloat162float(h2), xn3 - __bfloat162float(h3));

    float e = xn0 * we.x + xn1 * we.y + xn2 * we.z + xn3 * we.w;
#pragma unroll
    for (int off = 16; off; off >>= 1) e += __shfl_xor_sync(0xffffffffu, e, off);
    if ((tid & 31) == 0) sbuf[tid >> 5] = e;
    __syncthreads();
    if (tid == 0) {
        float et = 0.f;
#pragma unroll
        for (int i = 0; i < 8; i++) et += sbuf[i];
        float gt = 1.f / (1.f + __expf(-(et + b_ent[0])));
        g_gate[t] = fminf(fmaxf(gt, 0.1f), 2.0f);
    }
}

// ============================================================
// Kernel 2: bf16x3 GEMM on pre-split inputs, cp.async 2-stage.
// C = A @ Bw^T + bias; mode fp32 (Cf, alpha) or split-bf16 (Ch/Cl,
// with gate applied to cols >= gcol0 before splitting).
// BM=BN=128, BK=32, 256 threads, 2 CTAs/SM.
// GSTR=40 bf16 -> 80B row stride (16B-aligned for cp.async.16).
// ============================================================
#define GSTR 40
#define GTILE (128 * GSTR)
#define GSTAGE (4 * GTILE)
#define G_SMEM (2 * GSTAGE * 2)   /* 81920 B */

__global__ __launch_bounds__(256, 2) void bf16x3_gemm2(
    const __nv_bfloat16* __restrict__ Ah_, const __nv_bfloat16* __restrict__ Al_,
    const __nv_bfloat16* __restrict__ Bh_, const __nv_bfloat16* __restrict__ Bl_,
    const float* __restrict__ bias, const float* __restrict__ gate, int gcol0,
    float* __restrict__ Cf, __nv_bfloat16* __restrict__ Ch, __nv_bfloat16* __restrict__ Cl,
    int M, int N, int K, float alpha)
{
    extern __shared__ __nv_bfloat16 sg[];
    const int tid = threadIdx.x;
    const int wid = tid >> 5, lane = tid & 31;
    const int g = lane >> 2, tg = lane & 3;
    const int wm = (wid >> 2) * 64, wn = (wid & 3) * 32;
    const int m0 = blockIdx.y * 128, n0 = blockIdx.x * 128;

    const __nv_bfloat16* gsrc[4] = {Ah_, Al_, Bh_, Bl_};
    const int rbase[4] = {m0, m0, n0, n0};

    float acc[4][4][4];
#pragma unroll
    for (int mt = 0; mt < 4; mt++)
#pragma unroll
        for (int nt = 0; nt < 4; nt++)
#pragma unroll
            for (int q = 0; q < 4; q++) acc[mt][nt][q] = 0.f;

    const int NC = K >> 5;

#define G_FILL(ST, K0) do { \
    __nv_bfloat16* stp = sg + (ST) * GSTAGE; \
    _Pragma("unroll") \
    for (int sel = 0; sel < 4; sel++) { \
        _Pragma("unroll") \
        for (int half = 0; half < 2; half++) { \
            const int id = tid + half * 256; \
            const int row = id >> 2, ch = id & 3; \
            const __nv_bfloat16* src = gsrc[sel] + (size_t)(rbase[sel] + row) * K + (K0) + ch * 8; \
            uint32_t dst = (uint32_t)__cvta_generic_to_shared(stp + sel * GTILE + row * GSTR + ch * 8); \
            asm volatile("cp.async.cg.shared.global [%0], [%1], 16;" :: "r"(dst), "l"(src)); \
        } \
    } \
    asm volatile("cp.async.commit_group;" ::: "memory"); \
} while (0)

    G_FILL(0, 0);

    for (int c = 0; c < NC; c++) {
        if (c + 1 < NC) {
            G_FILL((c + 1) & 1, (c + 1) << 5);
            asm volatile("cp.async.wait_group 1;" ::: "memory");
        } else {
            asm volatile("cp.async.wait_group 0;" ::: "memory");
        }
        __syncthreads();

        const __nv_bfloat16* Ah = sg + (c & 1) * GSTAGE;
        const __nv_bfloat16* Al = Ah + GTILE;
        const __nv_bfloat16* Bh = Ah + 2 * GTILE;
        const __nv_bfloat16* Bl = Ah + 3 * GTILE;

#pragma unroll
        for (int kk = 0; kk < 32; kk += 16) {
            uint32_t ah[4][4], al[4][4];
#pragma unroll
            for (int mt = 0; mt < 4; mt++) {
                const int o0 = (wm + mt * 16 + g) * GSTR + kk + tg * 2;
                const int o1 = o0 + 8 * GSTR;
                ah[mt][0] = *(const uint32_t*)&Ah[o0];
                ah[mt][1] = *(const uint32_t*)&Ah[o1];
                ah[mt][2] = *(const uint32_t*)&Ah[o0 + 8];
                ah[mt][3] = *(const uint32_t*)&Ah[o1 + 8];
                al[mt][0] = *(const uint32_t*)&Al[o0];
                al[mt][1] = *(const uint32_t*)&Al[o1];
                al[mt][2] = *(const uint32_t*)&Al[o0 + 8];
                al[mt][3] = *(const uint32_t*)&Al[o1 + 8];
            }
#pragma unroll
            for (int nt = 0; nt < 4; nt++) {
                uint32_t bh[2], bl[2];
                const int ob = (wn + nt * 8 + g) * GSTR + kk + tg * 2;
                bh[0] = *(const uint32_t*)&Bh[ob];
                bh[1] = *(const uint32_t*)&Bh[ob + 8];
                bl[0] = *(const uint32_t*)&Bl[ob];
                bl[1] = *(const uint32_t*)&Bl[ob + 8];
#pragma unroll
                for (int mt = 0; mt < 4; mt++) {
                    MMA_BF16(acc[mt][nt], ah[mt], bh);
                    MMA_BF16(acc[mt][nt], ah[mt], bl);
                    MMA_BF16(acc[mt][nt], al[mt], bh);
                }
            }
        }
        __syncthreads();
    }

    // epilogue
#pragma unroll
    for (int mt = 0; mt < 4; mt++) {
        const int r0 = m0 + wm + mt * 16 + g;
#pragma unroll
        for (int nt = 0; nt < 4; nt++) {
            const int col = n0 + wn + nt * 8 + tg * 2;
            float v0 = acc[mt][nt][0] + bias[col];
            float v1 = acc[mt][nt][1] + bias[col + 1];
            float v2 = acc[mt][nt][2] + bias[col];
            float v3 = acc[mt][nt][3] + bias[col + 1];
            if (Cf) {
                float2 o;
                o.x = alpha * v0; o.y = alpha * v1;
                *(float2*)(Cf + (size_t)r0 * N + col) = o;
                o.x = alpha * v2; o.y = alpha * v3;
                *(float2*)(Cf + (size_t)(r0 + 8) * N + col) = o;
            } else {
                if (gate && col >= gcol0) {
                    const float g0 = gate[r0], g1 = gate[r0 + 8];
                    v0 *= g0; v1 *= g0; v2 *= g1; v3 *= g1;
                }
                __nv_bfloat16 h0 = __float2bfloat16(v0);
                __nv_bfloat16 h1 = __float2bfloat16(v1);
                __nv_bfloat16 h2 = __float2bfloat16(v2);
                __nv_bfloat16 h3 = __float2bfloat16(v3);
                const size_t oA = (size_t)r0 * N + col;
                const size_t oB = (size_t)(r0 + 8) * N + col;
                *(uint32_t*)&Ch[oA] = pack2bf(__bfloat162float(h0), __bfloat162float(h1));
                *(uint32_t*)&Ch[oB] = pack2bf(__bfloat162float(h2), __bfloat162float(h3));
                *(uint32_t*)&Cl[oA] = pack2bf(v0 - __bfloat162float(h0), v1 - __bfloat162float(h1));
                *(uint32_t*)&Cl[oB] = pack2bf(v2 - __bfloat162float(h2), v3 - __bfloat162float(h3));
            }
        }
    }
}

// ============================================================
// Kernel 3: mma.sync causal flash attention on pre-split bf16 qkv.
// QK^T = bf16x3; PV = bf16x3; gate pre-folded into V at QKV epilogue.
// ============================================================
#define KSTR 72
#define VSTR 72
#define ATT_SMEM (4 * 64 * 72 * 2)   /* 36864 B */

__global__ __launch_bounds__(256, 1) void attn_mma(void)
{
    extern __shared__ __nv_bfloat16 sb[];
    __nv_bfloat16* Kh = sb;
    __nv_bfloat16* Kl = sb + 64 * KSTR;
    __nv_bfloat16* Vh = sb + 2 * 64 * KSTR;   // transposed [d][key]
    __nv_bfloat16* Vl = sb + 3 * 64 * KSTR;

    const int qt  = gridDim.x - 1 - blockIdx.x;
    const int h   = blockIdx.y, b = blockIdx.z;
    const int tid = threadIdx.x;
    const int wid = tid >> 5;
    const int lane = tid & 31;
    const int gi = lane >> 2;
    const int tg = lane & 3;
    const int q0 = qt * 128;
    const float scl = 1.25f;

    // ---- stage Q (copy pre-split bf16), then load fragments ----
    {
        __nv_bfloat16* Qh = sb;
        __nv_bfloat16* Ql = sb + 128 * KSTR;
#pragma unroll
        for (int i = 0; i < 8; i++) {
            const int idx = tid + (i & 3) * 256;
            const int row = idx >> 3, c8 = idx & 7;
            const __nv_bfloat16* src = (i < 4 ? g_qkvh : g_qkvl)
                + (size_t)(b * SEQ + q0 + row) * 3072 + h * 64 + c8 * 8;
            __nv_bfloat16* dst = (i < 4 ? Qh : Ql) + row * KSTR + c8 * 8;
            *(uint4*)dst = *(const uint4*)src;
        }
    }
    __syncthreads();

    uint32_t qh[4][4], ql[4][4];
    {
        const __nv_bfloat16* Qh = sb;
        const __nv_bfloat16* Ql = sb + 128 * KSTR;
        const int r0 = 16 * wid + gi;
#pragma unroll
        for (int ds = 0; ds < 4; ds++) {
            const int k = ds * 16 + tg * 2;
            qh[ds][0] = *(const uint32_t*)&Qh[r0 * KSTR + k];
            qh[ds][1] = *(const uint32_t*)&Qh[(r0 + 8) * KSTR + k];
            qh[ds][2] = *(const uint32_t*)&Qh[r0 * KSTR + k + 8];
            qh[ds][3] = *(const uint32_t*)&Qh[(r0 + 8) * KSTR + k + 8];
            ql[ds][0] = *(const uint32_t*)&Ql[r0 * KSTR + k];
            ql[ds][1] = *(const uint32_t*)&Ql[(r0 + 8) * KSTR + k];
            ql[ds][2] = *(const uint32_t*)&Ql[r0 * KSTR + k + 8];
            ql[ds][3] = *(const uint32_t*)&Ql[(r0 + 8) * KSTR + k + 8];
        }
    }
    __syncthreads();

    float m0v = -INFINITY, m1v = -INFINITY, l0v = 0.f, l1v = 0.f;
    float acc_o[8][4];
#pragma unroll
    for (int nt = 0; nt < 8; nt++)
#pragma unroll
        for (int q = 0; q < 4; q++) acc_o[nt][q] = 0.f;

    const int row0 = q0 + 16 * wid + gi;
    const int row1 = row0 + 8;
    const int rmax = q0 + 16 * wid + 15;
    const int nkt = 2 * qt + 2;

    for (int kt = 0; kt < nkt; kt++) {
        const int k0 = kt * 64;

        // ---- K fill ----
#pragma unroll
        for (int i = 0; i < 4; i++) {
            const int idx = tid + (i & 1) * 256;
            const int key = idx >> 3, c8 = idx & 7;
            const __nv_bfloat16* src = (i < 2 ? g_qkvh : g_qkvl)
                + (size_t)(b * SEQ + k0 + key) * 3072 + 1024 + h * 64 + c8 * 8;
            __nv_bfloat16* dst = (i < 2 ? Kh : Kl) + key * KSTR + c8 * 8;
            *(uint4*)dst = *(const uint4*)src;
        }
        // ---- V fill: key-pair transpose ----
        {
            const int kp = tid & 31, c8 = tid >> 5;
#pragma unroll
            for (int i = 0; i < 2; i++) {
                const __nv_bfloat16* src = (i == 0 ? g_qkvh : g_qkvl)
                    + (size_t)(b * SEQ + k0 + 2 * kp) * 3072 + 2048 + h * 64 + c8 * 8;
                uint4 ua = *(const uint4*)src;
                uint4 ub = *(const uint4*)(src + 3072);
                const __nv_bfloat16* va = (const __nv_bfloat16*)&ua;
                const __nv_bfloat16* vb = (const __nv_bfloat16*)&ub;
                __nv_bfloat16* Vt = (i == 0 ? Vh : Vl);
#pragma unroll
                for (int j = 0; j < 8; j++) {
                    __nv_bfloat162 p;
                    p.x = va[j]; p.y = vb[j];
                    *(__nv_bfloat162*)&Vt[(c8 * 8 + j) * VSTR + 2 * kp] = p;
                }
            }
        }
        __syncthreads();

        if (k0 <= rmax) {
            // ---- QK^T (bf16x3) ----
            float s[8][4];
#pragma unroll
            for (int nt = 0; nt < 8; nt++)
#pragma unroll
                for (int q = 0; q < 4; q++) s[nt][q] = 0.f;

#pragma unroll
            for (int ds = 0; ds < 4; ds++) {
                const int kk = ds * 16 + tg * 2;
#pragma unroll
                for (int nt = 0; nt < 8; nt++) {
                    uint32_t bh[2], bl[2];
                    const int o = (nt * 8 + gi) * KSTR + kk;
                    bh[0] = *(const uint32_t*)&Kh[o];
                    bh[1] = *(const uint32_t*)&Kh[o + 8];
                    bl[0] = *(const uint32_t*)&Kl[o];
                    bl[1] = *(const uint32_t*)&Kl[o + 8];
                    MMA_BF16(s[nt], qh[ds], bh);
                    MMA_BF16(s[nt], qh[ds], bl);
                    MMA_BF16(s[nt], ql[ds], bh);
                }
            }

#pragma unroll
            for (int nt = 0; nt < 8; nt++)
#pragma unroll
                for (int q = 0; q < 4; q++) s[nt][q] *= scl;
            if (kt >= 2 * qt) {
#pragma unroll
                for (int nt = 0; nt < 8; nt++) {
                    const int c0 = k0 + nt * 8 + tg * 2;
                    if (c0     > row0) s[nt][0] = -INFINITY;
                    if (c0 + 1 > row0) s[nt][1] = -INFINITY;
                    if (c0     > row1) s[nt][2] = -INFINITY;
                    if (c0 + 1 > row1) s[nt][3] = -INFINITY;
                }
            }

            // ---- online softmax ----
            float mx0 = -INFINITY, mx1 = -INFINITY;
#pragma unroll
            for (int nt = 0; nt < 8; nt++) {
                mx0 = fmaxf(mx0, fmaxf(s[nt][0], s[nt][1]));
                mx1 = fmaxf(mx1, fmaxf(s[nt][2], s[nt][3]));
            }
            mx0 = fmaxf(mx0, __shfl_xor_sync(0xffffffffu, mx0, 1));
            mx0 = fmaxf(mx0, __shfl_xor_sync(0xffffffffu, mx0, 2));
            mx1 = fmaxf(mx1, __shfl_xor_sync(0xffffffffu, mx1, 1));
            mx1 = fmaxf(mx1, __shfl_xor_sync(0xffffffffu, mx1, 2));

            const float nm0 = fmaxf(m0v, mx0);
            const float nm1 = fmaxf(m1v, mx1);
            const float al0 = __expf(m0v - nm0);
            const float al1 = __expf(m1v - nm1);
            float rs0 = 0.f, rs1 = 0.f;
#pragma unroll
            for (int nt = 0; nt < 8; nt++) {
                s[nt][0] = __expf(s[nt][0] - nm0);
                s[nt][1] = __expf(s[nt][1] - nm0);
                s[nt][2] = __expf(s[nt][2] - nm1);
                s[nt][3] = __expf(s[nt][3] - nm1);
                rs0 += s[nt][0] + s[nt][1];
                rs1 += s[nt][2] + s[nt][3];
            }
            rs0 += __shfl_xor_sync(0xffffffffu, rs0, 1);
            rs0 += __shfl_xor_sync(0xffffffffu, rs0, 2);
            rs1 += __shfl_xor_sync(0xffffffffu, rs1, 1);
            rs1 += __shfl_xor_sync(0xffffffffu, rs1, 2);
            l0v = l0v * al0 + rs0;
            l1v = l1v * al1 + rs1;
            m0v = nm0; m1v = nm1;
#pragma unroll
            for (int nt = 0; nt < 8; nt++) {
                acc_o[nt][0] *= al0; acc_o[nt][1] *= al0;
                acc_o[nt][2] *= al1; acc_o[nt][3] *= al1;
            }

            // ---- PV (bf16x3) ----
#pragma unroll
            for (int s4 = 0; s4 < 4; s4++) {
                uint32_t pa[4], pl[4];
                {
                    const float p00 = s[2 * s4][0],     p01 = s[2 * s4][1];
                    const float p02 = s[2 * s4][2],     p03 = s[2 * s4][3];
                    const float p10 = s[2 * s4 + 1][0], p11 = s[2 * s4 + 1][1];
                    const float p12 = s[2 * s4 + 1][2], p13 = s[2 * s4 + 1][3];
                    pa[0] = pack2bf(p00, p01);
                    pa[1] = pack2bf(p02, p03);
                    pa[2] = pack2bf(p10, p11);
                    pa[3] = pack2bf(p12, p13);
                    __nv_bfloat162* ph;
                    ph = (__nv_bfloat162*)&pa[0];
                    pl[0] = pack2bf(p00 - __bfloat162float(ph->x), p01 - __bfloat162float(ph->y));
                    ph = (__nv_bfloat162*)&pa[1];
                    pl[1] = pack2bf(p02 - __bfloat162float(ph->x), p03 - __bfloat162float(ph->y));
                    ph = (__nv_bfloat162*)&pa[2];
                    pl[2] = pack2bf(p10 - __bfloat162float(ph->x), p11 - __bfloat162float(ph->y));
                    ph = (__nv_bfloat162*)&pa[3];
                    pl[3] = pack2bf(p12 - __bfloat162float(ph->x), p13 - __bfloat162float(ph->y));
                }
                const int kk = s4 * 16 + tg * 2;
#pragma unroll
                for (int nt = 0; nt < 8; nt++) {
                    uint32_t bvh[2], bvl[2];
                    const int o = (nt * 8 + gi) * VSTR + kk;
                    bvh[0] = *(const uint32_t*)&Vh[o];
                    bvh[1] = *(const uint32_t*)&Vh[o + 8];
                    bvl[0] = *(const uint32_t*)&Vl[o];
                    bvl[1] = *(const uint32_t*)&Vl[o + 8];
                    MMA_BF16(acc_o[nt], pa, bvh);
                    MMA_BF16(acc_o[nt], pa, bvl);
                    MMA_BF16(acc_o[nt], pl, bvh);
                }
            }
        }
        __syncthreads();
    }

    // ---- epilogue: split output to bf16 hi/lo ----
    const float inv0 = 1.f / l0v;
    const float inv1 = 1.f / l1v;
#pragma unroll
    for (int nt = 0; nt < 8; nt++) {
        const int col = h * 64 + nt * 8 + tg * 2;
        const float o0 = acc_o[nt][0] * inv0, o1 = acc_o[nt][1] * inv0;
        const float o2 = acc_o[nt][2] * inv1, o3 = acc_o[nt][3] * inv1;
        __nv_bfloat16 h0 = __float2bfloat16(o0);
        __nv_bfloat16 h1 = __float2bfloat16(o1);
        __nv_bfloat16 h2 = __float2bfloat16(o2);
        __nv_bfloat16 h3 = __float2bfloat16(o3);
        const size_t oA = (size_t)(b * SEQ + row0) * HSZ + col;
        const size_t oB = (size_t)(b * SEQ + row1) * HSZ + col;
        *(uint32_t*)&g_atth[oA] = pack2bf(__bfloat162float(h0), __bfloat162float(h1));
        *(uint32_t*)&g_atth[oB] = pack2bf(__bfloat162float(h2), __bfloat162float(h3));
        *(uint32_t*)&g_attl[oA] = pack2bf(o0 - __bfloat162float(h0), o1 - __bfloat162float(h1));
        *(uint32_t*)&g_attl[oB] = pack2bf(o2 - __bfloat162float(h2), o3 - __bfloat162float(h3));
    }
}

// ============================================================
// host launcher
// ============================================================
extern "C" void kernel_launch(void* const* d_in, const int* in_sizes, int n_in,
                              void* d_out, int out_size)
{
    const float* x     = (const float*)d_in[0];
    const float* ln_g  = (const float*)d_in[1];
    const float* ln_b  = (const float*)d_in[2];
    const float* w_qkv = (const float*)d_in[3];
    const float* b_qkv = (const float*)d_in[4];
    const float* w_ent = (const float*)d_in[5];
    const float* b_ent = (const float*)d_in[6];
    const float* w_out = (const float*)d_in[7];
    const float* b_out = (const float*)d_in[8];
    float* out = (float*)d_out;

    void *p_xh, *p_xl, *p_gate, *p_wqh, *p_wql, *p_woh, *p_wol;
    void *p_qkvh, *p_qkvl, *p_atth, *p_attl;
    cudaGetSymbolAddress(&p_xh,   g_xh);
    cudaGetSymbolAddress(&p_xl,   g_xl);
    cudaGetSymbolAddress(&p_gate, g_gate);
    cudaGetSymbolAddress(&p_wqh,  g_wqh);
    cudaGetSymbolAddress(&p_wql,  g_wql);
    cudaGetSymbolAddress(&p_woh,  g_woh);
    cudaGetSymbolAddress(&p_wol,  g_wol);
    cudaGetSymbolAddress(&p_qkvh, g_qkvh);
    cudaGetSymbolAddress(&p_qkvl, g_qkvl);
    cudaGetSymbolAddress(&p_atth, g_atth);
    cudaGetSymbolAddress(&p_attl, g_attl);

    cudaFuncSetAttribute(bf16x3_gemm2, cudaFuncAttributeMaxDynamicSharedMemorySize, G_SMEM);
    cudaFuncSetAttribute(attn_mma, cudaFuncAttributeMaxDynamicSharedMemorySize, ATT_SMEM);

    // 0) pre-split weights
    wsplit<<<(3 * HSZ * HSZ / 4 + 255) / 256, 256>>>(
        w_qkv, (__nv_bfloat16*)p_wqh, (__nv_bfloat16*)p_wql, 3 * HSZ * HSZ / 4);
    wsplit<<<(HSZ * HSZ / 4 + 255) / 256, 256>>>(
        w_out, (__nv_bfloat16*)p_woh, (__nv_bfloat16*)p_wol, HSZ * HSZ / 4);

    // 1) LN + entropy gate (writes split xn)
    ln_gate_kernel<<<NTOK, 256>>>(x, ln_g, ln_b, w_ent, b_ent);

    // 2) QKV projection -> split bf16 qkv, gate folded into V cols
    bf16x3_gemm2<<<dim3(3 * HSZ / 128, NTOK / 128), 256, G_SMEM>>>(
        (const __nv_bfloat16*)p_xh, (const __nv_bfloat16*)p_xl,
        (const __nv_bfloat16*)p_wqh, (const __nv_bfloat16*)p_wql,
        b_qkv, (const float*)p_gate, 2048,
        nullptr, (__nv_bfloat16*)p_qkvh, (__nv_bfloat16*)p_qkvl,
        NTOK, 3 * HSZ, HSZ, 1.0f);

    // 3) attention
    attn_mma<<<dim3(SEQ / 128, NHEADS, BATCH), 256, ATT_SMEM>>>();

    // 4) output projection (fp32 out, alpha=0.1)
    bf16x3_gemm2<<<dim3(HSZ / 128, NTOK / 128), 256, G_SMEM>>>(
        (const __nv_bfloat16*)p_atth, (const __nv_bfloat16*)p_attl,
        (const __nv_bfloat16*)p_woh, (const __nv_bfloat16*)p_wol,
        b_out, nullptr, 1 << 30,
        out, nullptr, nullptr,
        NTOK, HSZ, HSZ, 0.1f);
}